// round 12
// baseline (speedup 1.0000x reference)
#include <cuda_runtime.h>
#include <math.h>
#include <stdint.h>

// ---------------- problem constants ----------------
#define CAMS   6
#define HEADS  8
#define PTS    2
#define LAYERS 3
#define Dm     256
#define DHh    32
#define FFNd   512
#define NQ     20000
#define IN_C   768
#define FH     8
#define FW     22
#define Lf     176
#define LVIS   44
#define NSP    20000          // 50*50*8  (deconv input spatial)
#define SP     160000         // 100*100*16 (deconv output spatial)
#define X_ELEMS   (192*SP)
#define CAMX_ELEMS (CAMS*IN_C*Lf)

// ---------------- scratch (static device memory; no allocations) ----------------
__device__ float g_full [CAMS*Lf*IN_C];
__device__ float g_feat [CAMS*Lf*Dm];
__device__ float g_valb [CAMS*Lf*Dm];
__device__ float g_q    [NQ*Dm];
__device__ float g_off  [NQ*HEADS*CAMS*PTS*2];
__device__ float g_att  [NQ*HEADS*CAMS*PTS];
__device__ float g_agg  [NQ*Dm];
__device__ float g_hid  [NQ*FFNd];
__device__ float g_delta[NQ*Dm];
__device__ float g_vol  [Dm*NSP];
__device__ float g_x1   [Dm*SP];
__device__ float g_wp   [27*256*192];      // conv3 weights prepacked [tap][ic][oc], tf32
__device__ float g_psum [1024];
__device__ float g_psq  [1024];
__device__ float g_mean [16];
__device__ float g_rstd [16];
__device__ float g_scale[256];             // GN1 fused per-channel scale
__device__ float g_shift[256];             // GN1 fused per-channel shift

__device__ __forceinline__ uint32_t f2tf32(float v) {
    uint32_t o;
    asm("cvt.rna.tf32.f32 %0, %1;" : "=r"(o) : "f"(v));
    return o;
}
#define MMA_TF32(acc, af, b0, b1) \
    asm volatile( \
        "mma.sync.aligned.m16n8k8.row.col.f32.tf32.tf32.f32 " \
        "{%0,%1,%2,%3}, {%4,%5,%6,%7}, {%8,%9}, {%0,%1,%2,%3};" \
        : "+f"((acc)[0]), "+f"((acc)[1]), "+f"((acc)[2]), "+f"((acc)[3]) \
        : "r"((af)[0]), "r"((af)[1]), "r"((af)[2]), "r"((af)[3]), \
          "r"(b0), "r"(b1))

// ---------------- kernel 1: restore full tokens + emit cam_x ----------------
__global__ void k_build_full(const float* __restrict__ cx, const int* __restrict__ ids,
                             const float* __restrict__ mt, float* __restrict__ full,
                             float* __restrict__ camx, int write_camx)
{
    int i = blockIdx.x * blockDim.x + threadIdx.x;
    if (i >= CAMS*Lf*IN_C) return;
    int c = i % IN_C;
    int l = (i / IN_C) % Lf;
    int n = i / (IN_C*Lf);
    int id = ids[n*Lf + l];
    float v = (id < LVIS) ? cx[((size_t)n*LVIS + id)*IN_C + c] : mt[c];
    full[i] = v;
    if (write_camx)
        camx[((size_t)n*IN_C + c)*Lf + l] = v;
}

// ---------------- generic tiled SGEMM: C = A(MxK) * B(KxN) ----------------
__global__ __launch_bounds__(256)
void k_sgemm_nn(const float* __restrict__ A, const float* __restrict__ B,
                const float* __restrict__ bias, float* __restrict__ C,
                int M, int N, int K, int relu)
{
    __shared__ float As[16][64];
    __shared__ float Bs[16][68];
    int m0 = blockIdx.y * 64, n0 = blockIdx.x * 64;
    int t = threadIdx.x, ty = t >> 4, tx = t & 15;
    float acc[4][4] = {};
    int am = t >> 2, ak = (t & 3) << 2;
    int bk = ty,     bn = tx << 2;

    for (int k0 = 0; k0 < K; k0 += 16) {
        float4 av = make_float4(0.f,0.f,0.f,0.f);
        if (m0 + am < M) av = *(const float4*)(A + (size_t)(m0+am)*K + k0 + ak);
        As[ak+0][am] = av.x; As[ak+1][am] = av.y; As[ak+2][am] = av.z; As[ak+3][am] = av.w;
        float4 bv = make_float4(0.f,0.f,0.f,0.f);
        if (n0 + bn < N) bv = *(const float4*)(B + (size_t)(k0+bk)*N + n0 + bn);
        *(float4*)&Bs[bk][bn] = bv;
        __syncthreads();
        #pragma unroll
        for (int kk = 0; kk < 16; kk++) {
            float4 a = *(const float4*)&As[kk][ty<<2];
            float4 b = *(const float4*)&Bs[kk][tx<<2];
            float av4[4] = {a.x,a.y,a.z,a.w};
            float bv4[4] = {b.x,b.y,b.z,b.w};
            #pragma unroll
            for (int i = 0; i < 4; i++)
                #pragma unroll
                for (int j = 0; j < 4; j++)
                    acc[i][j] += av4[i]*bv4[j];
        }
        __syncthreads();
    }
    #pragma unroll
    for (int i = 0; i < 4; i++) {
        int m = m0 + (ty<<2) + i;
        if (m >= M) continue;
        #pragma unroll
        for (int j = 0; j < 4; j++) {
            int n = n0 + (tx<<2) + j;
            if (n >= N) continue;
            float v = acc[i][j] + (bias ? bias[n] : 0.f);
            if (relu) v = fmaxf(v, 0.f);
            C[(size_t)m*N + n] = v;
        }
    }
}

// ---------------- SGEMM with B transposed ----------------
__global__ __launch_bounds__(256)
void k_sgemm_nt(const float* __restrict__ A, const float* __restrict__ B,
                const float* __restrict__ bias, float* __restrict__ C,
                int M, int N, int K, int relu)
{
    __shared__ float As[16][64];
    __shared__ float Bs[16][68];
    int m0 = blockIdx.y * 64, n0 = blockIdx.x * 64;
    int t = threadIdx.x, ty = t >> 4, tx = t & 15;
    float acc[4][4] = {};
    int lr = t >> 2, lk = (t & 3) << 2;

    for (int k0 = 0; k0 < K; k0 += 16) {
        float4 av = make_float4(0.f,0.f,0.f,0.f);
        if (m0 + lr < M) av = *(const float4*)(A + (size_t)(m0+lr)*K + k0 + lk);
        As[lk+0][lr] = av.x; As[lk+1][lr] = av.y; As[lk+2][lr] = av.z; As[lk+3][lr] = av.w;
        float4 bv = make_float4(0.f,0.f,0.f,0.f);
        if (n0 + lr < N) bv = *(const float4*)(B + (size_t)(n0+lr)*K + k0 + lk);
        Bs[lk+0][lr] = bv.x; Bs[lk+1][lr] = bv.y; Bs[lk+2][lr] = bv.z; Bs[lk+3][lr] = bv.w;
        __syncthreads();
        #pragma unroll
        for (int kk = 0; kk < 16; kk++) {
            float4 a = *(const float4*)&As[kk][ty<<2];
            float4 b = *(const float4*)&Bs[kk][tx<<2];
            float av4[4] = {a.x,a.y,a.z,a.w};
            float bv4[4] = {b.x,b.y,b.z,b.w};
            #pragma unroll
            for (int i = 0; i < 4; i++)
                #pragma unroll
                for (int j = 0; j < 4; j++)
                    acc[i][j] += av4[i]*bv4[j];
        }
        __syncthreads();
    }
    #pragma unroll
    for (int i = 0; i < 4; i++) {
        int m = m0 + (ty<<2) + i;
        if (m >= M) continue;
        #pragma unroll
        for (int j = 0; j < 4; j++) {
            int n = n0 + (tx<<2) + j;
            if (n >= N) continue;
            float v = acc[i][j] + (bias ? bias[n] : 0.f);
            if (relu) v = fmaxf(v, 0.f);
            C[(size_t)m*N + n] = v;
        }
    }
}

// ---------------- tf32 mma GEMM (double-buffered): C = A x B + bias ----------------
// CTA 128M x 64N, 8 warps = 4(m) x 2(n), warp tile 32x32 = 2x4 m16n8k8.
__global__ __launch_bounds__(256)
void k_gemm_tf32(const float* __restrict__ A, const float* __restrict__ B,
                 const float* __restrict__ bias, float* __restrict__ C,
                 int M, int N, int K, int relu)
{
    __shared__ float As[2][128*17];
    __shared__ float Bs[2][16][68];
    int t = threadIdx.x;
    int wid = t >> 5, l = t & 31;
    int warp_m = wid & 3, warp_n = wid >> 2;
    int qrow = l >> 2, qcol = l & 3;
    int m0 = blockIdx.y * 128, n0 = blockIdx.x * 64;

    float acc[2][4][4];
    #pragma unroll
    for (int a = 0; a < 2; a++)
        #pragma unroll
        for (int b = 0; b < 4; b++)
            #pragma unroll
            for (int c = 0; c < 4; c++) acc[a][b][c] = 0.f;

    float ldA[8], ldB[4];
    int nk = K >> 4;

    // load chunk 0
    #pragma unroll
    for (int i = 0; i < 8; i++) {
        int e = i*256 + t, m = e >> 4, k = e & 15;
        ldA[i] = (m0 + m < M) ? A[(size_t)(m0+m)*K + k] : 0.f;
    }
    #pragma unroll
    for (int i = 0; i < 4; i++) {
        int e = i*256 + t, k = e >> 6, n = e & 63;
        ldB[i] = (n0 + n < N) ? B[(size_t)k*N + n0 + n] : 0.f;
    }
    // store chunk 0 -> buf 0
    #pragma unroll
    for (int i = 0; i < 8; i++) {
        int e = i*256 + t, m = e >> 4, k = e & 15;
        As[0][m*17 + k] = __uint_as_float(f2tf32(ldA[i]));
    }
    #pragma unroll
    for (int i = 0; i < 4; i++) {
        int e = i*256 + t, k = e >> 6, n = e & 63;
        Bs[0][k][n] = __uint_as_float(f2tf32(ldB[i]));
    }
    // load chunk 1
    if (nk > 1) {
        #pragma unroll
        for (int i = 0; i < 8; i++) {
            int e = i*256 + t, m = e >> 4, k = e & 15;
            ldA[i] = (m0 + m < M) ? A[(size_t)(m0+m)*K + 16 + k] : 0.f;
        }
        #pragma unroll
        for (int i = 0; i < 4; i++) {
            int e = i*256 + t, k = e >> 6, n = e & 63;
            ldB[i] = (n0 + n < N) ? B[(size_t)(16+k)*N + n0 + n] : 0.f;
        }
    }
    __syncthreads();

    for (int c = 0; c < nk; c++) {
        int cur = c & 1, nxt = cur ^ 1;
        if (c + 1 < nk) {                         // store chunk c+1 into idle buf
            #pragma unroll
            for (int i = 0; i < 8; i++) {
                int e = i*256 + t, m = e >> 4, k = e & 15;
                As[nxt][m*17 + k] = __uint_as_float(f2tf32(ldA[i]));
            }
            #pragma unroll
            for (int i = 0; i < 4; i++) {
                int e = i*256 + t, k = e >> 6, n = e & 63;
                Bs[nxt][k][n] = __uint_as_float(f2tf32(ldB[i]));
            }
        }
        if (c + 2 < nk) {                         // prefetch chunk c+2
            int k0 = (c + 2) << 4;
            #pragma unroll
            for (int i = 0; i < 8; i++) {
                int e = i*256 + t, m = e >> 4, k = e & 15;
                ldA[i] = (m0 + m < M) ? A[(size_t)(m0+m)*K + k0 + k] : 0.f;
            }
            #pragma unroll
            for (int i = 0; i < 4; i++) {
                int e = i*256 + t, k = e >> 6, n = e & 63;
                ldB[i] = (n0 + n < N) ? B[(size_t)(k0+k)*N + n0 + n] : 0.f;
            }
        }
        #pragma unroll
        for (int s8 = 0; s8 < 2; s8++) {
            uint32_t af[2][4];
            #pragma unroll
            for (int mt = 0; mt < 2; mt++) {
                int m = warp_m*32 + mt*16;
                int kb = s8*8 + qcol;
                af[mt][0] = __float_as_uint(As[cur][(m+qrow  )*17 + kb    ]);
                af[mt][1] = __float_as_uint(As[cur][(m+qrow+8)*17 + kb    ]);
                af[mt][2] = __float_as_uint(As[cur][(m+qrow  )*17 + kb + 4]);
                af[mt][3] = __float_as_uint(As[cur][(m+qrow+8)*17 + kb + 4]);
            }
            #pragma unroll
            for (int nt = 0; nt < 4; nt++) {
                int n = warp_n*32 + nt*8 + qrow;
                uint32_t b0 = __float_as_uint(Bs[cur][s8*8 + qcol    ][n]);
                uint32_t b1 = __float_as_uint(Bs[cur][s8*8 + qcol + 4][n]);
                #pragma unroll
                for (int mt = 0; mt < 2; mt++)
                    MMA_TF32(acc[mt][nt], af[mt], b0, b1);
            }
        }
        __syncthreads();
    }

    #pragma unroll
    for (int mt = 0; mt < 2; mt++) {
        int mrow = m0 + warp_m*32 + mt*16 + qrow;
        #pragma unroll
        for (int nt = 0; nt < 4; nt++) {
            int n = n0 + warp_n*32 + nt*8 + qcol*2;
            if (n >= N) continue;
            float b0v = bias ? bias[n]   : 0.f;
            float b1v = bias ? bias[n+1] : 0.f;
            float v0 = acc[mt][nt][0] + b0v, v1 = acc[mt][nt][1] + b1v;
            float v2 = acc[mt][nt][2] + b0v, v3 = acc[mt][nt][3] + b1v;
            if (relu) { v0=fmaxf(v0,0.f); v1=fmaxf(v1,0.f); v2=fmaxf(v2,0.f); v3=fmaxf(v3,0.f); }
            if (mrow < M)     *(float2*)&C[(size_t)mrow*N + n]     = make_float2(v0, v1);
            if (mrow + 8 < M) *(float2*)&C[(size_t)(mrow+8)*N + n] = make_float2(v2, v3);
        }
    }
}

// ---------------- deconv via tf32 mma (double-buffered) ----------------
// grid (313, 2, 8). CTA 128 oc x 64 sp. Wd layout [oc][ic][tap] (stride 8).
__global__ __launch_bounds__(256)
void k_deconv_tf32(const float* __restrict__ Wd, const float* __restrict__ V,
                   float* __restrict__ X1)
{
    __shared__ float As[2][128*17];
    __shared__ float Bs[2][16][68];
    int t = threadIdx.x;
    int wid = t >> 5, l = t & 31;
    int warp_m = wid & 3, warp_n = wid >> 2;
    int qrow = l >> 2, qcol = l & 3;
    int m0 = blockIdx.y * 128, n0 = blockIdx.x * 64;
    int tap = blockIdx.z;
    int k1 = tap>>2, k2 = (tap>>1)&1, k3 = tap&1;

    float acc[2][4][4];
    #pragma unroll
    for (int a = 0; a < 2; a++)
        #pragma unroll
        for (int b = 0; b < 4; b++)
            #pragma unroll
            for (int c = 0; c < 4; c++) acc[a][b][c] = 0.f;

    float ldA[8], ldB[4];
    // chunk 0
    #pragma unroll
    for (int i = 0; i < 8; i++) {
        int e = i*256 + t, m = e >> 4, k = e & 15;
        ldA[i] = Wd[(((size_t)(m0+m))*256 + k)*8 + tap];
    }
    #pragma unroll
    for (int i = 0; i < 4; i++) {
        int e = i*256 + t, k = e >> 6, n = e & 63;
        ldB[i] = (n0 + n < NSP) ? V[(size_t)k*NSP + n0 + n] : 0.f;
    }
    #pragma unroll
    for (int i = 0; i < 8; i++) {
        int e = i*256 + t, m = e >> 4, k = e & 15;
        As[0][m*17 + k] = __uint_as_float(f2tf32(ldA[i]));
    }
    #pragma unroll
    for (int i = 0; i < 4; i++) {
        int e = i*256 + t, k = e >> 6, n = e & 63;
        Bs[0][k][n] = __uint_as_float(f2tf32(ldB[i]));
    }
    // chunk 1
    #pragma unroll
    for (int i = 0; i < 8; i++) {
        int e = i*256 + t, m = e >> 4, k = e & 15;
        ldA[i] = Wd[(((size_t)(m0+m))*256 + 16 + k)*8 + tap];
    }
    #pragma unroll
    for (int i = 0; i < 4; i++) {
        int e = i*256 + t, k = e >> 6, n = e & 63;
        ldB[i] = (n0 + n < NSP) ? V[(size_t)(16+k)*NSP + n0 + n] : 0.f;
    }
    __syncthreads();

    for (int c = 0; c < 16; c++) {       // K = 256
        int cur = c & 1, nxt = cur ^ 1;
        if (c + 1 < 16) {
            #pragma unroll
            for (int i = 0; i < 8; i++) {
                int e = i*256 + t, m = e >> 4, k = e & 15;
                As[nxt][m*17 + k] = __uint_as_float(f2tf32(ldA[i]));
            }
            #pragma unroll
            for (int i = 0; i < 4; i++) {
                int e = i*256 + t, k = e >> 6, n = e & 63;
                Bs[nxt][k][n] = __uint_as_float(f2tf32(ldB[i]));
            }
        }
        if (c + 2 < 16) {
            int k0 = (c + 2) << 4;
            #pragma unroll
            for (int i = 0; i < 8; i++) {
                int e = i*256 + t, m = e >> 4, k = e & 15;
                ldA[i] = Wd[(((size_t)(m0+m))*256 + k0 + k)*8 + tap];
            }
            #pragma unroll
            for (int i = 0; i < 4; i++) {
                int e = i*256 + t, k = e >> 6, n = e & 63;
                ldB[i] = (n0 + n < NSP) ? V[(size_t)(k0+k)*NSP + n0 + n] : 0.f;
            }
        }
        #pragma unroll
        for (int s8 = 0; s8 < 2; s8++) {
            uint32_t af[2][4];
            #pragma unroll
            for (int mt = 0; mt < 2; mt++) {
                int m = warp_m*32 + mt*16;
                int kb = s8*8 + qcol;
                af[mt][0] = __float_as_uint(As[cur][(m+qrow  )*17 + kb    ]);
                af[mt][1] = __float_as_uint(As[cur][(m+qrow+8)*17 + kb    ]);
                af[mt][2] = __float_as_uint(As[cur][(m+qrow  )*17 + kb + 4]);
                af[mt][3] = __float_as_uint(As[cur][(m+qrow+8)*17 + kb + 4]);
            }
            #pragma unroll
            for (int nt = 0; nt < 4; nt++) {
                int n = warp_n*32 + nt*8 + qrow;
                uint32_t b0 = __float_as_uint(Bs[cur][s8*8 + qcol    ][n]);
                uint32_t b1 = __float_as_uint(Bs[cur][s8*8 + qcol + 4][n]);
                #pragma unroll
                for (int mt = 0; mt < 2; mt++)
                    MMA_TF32(acc[mt][nt], af[mt], b0, b1);
            }
        }
        __syncthreads();
    }

    // scatter epilogue
    #pragma unroll
    for (int mt = 0; mt < 2; mt++) {
        int mrow = m0 + warp_m*32 + mt*16 + qrow;
        #pragma unroll
        for (int nt = 0; nt < 4; nt++) {
            int n = n0 + warp_n*32 + nt*8 + qcol*2;
            #pragma unroll
            for (int j = 0; j < 2; j++) {
                int col = n + j;
                if (col >= NSP) continue;
                int a_ = col/400, b_ = (col>>3)%50, c_ = col&7;
                size_t o = (size_t)(2*a_ + 1 - k1)*1600 + (2*b_ + 1 - k2)*16 + (2*c_ + 1 - k3);
                X1[(size_t)mrow*SP + o]     = acc[mt][nt][j];
                X1[(size_t)(mrow+8)*SP + o] = acc[mt][nt][2+j];
            }
        }
    }
}

// ---------------- feat += cams_embeds[cam] + level_embeds ----------------
__global__ void k_add_embeds(float* __restrict__ feat, const float* __restrict__ cams,
                             const float* __restrict__ lvl)
{
    int i = blockIdx.x * blockDim.x + threadIdx.x;
    if (i >= CAMS*Lf*Dm) return;
    int d = i % Dm;
    int n = i / (Lf*Dm);
    feat[i] += cams[n*Dm + d] + lvl[d];
}

// ---------------- deformable sampling with fused softmax ----------------
__global__ void k_sample(const float* __restrict__ val, const float* __restrict__ off,
                         const float* __restrict__ att, float* __restrict__ agg)
{
    int q = blockIdx.x;
    int h = threadIdx.y;
    int lane = threadIdx.x;
    float refx = ((float)(q % 50) + 0.5f) * (22.f/50.f) - 0.5f;
    float refy = ((float)((q/50) % 50) + 0.5f) * (8.f/50.f) - 0.5f;
    const float* offq = off + (size_t)q*192 + h*24;
    const float* attq = att + (size_t)q*96  + h*12;

    // warp-cooperative softmax over the 12 logits (one warp per head)
    float lg = (lane < 12) ? attq[lane] : -1e30f;
    float mx = lg;
    #pragma unroll
    for (int o = 16; o > 0; o >>= 1) mx = fmaxf(mx, __shfl_xor_sync(0xffffffffu, mx, o));
    float e = (lane < 12) ? expf(lg - mx) : 0.f;
    float ssum = e;
    #pragma unroll
    for (int o = 16; o > 0; o >>= 1) ssum += __shfl_xor_sync(0xffffffffu, ssum, o);
    float r = 1.f / ssum;

    float acc = 0.f;
    #pragma unroll
    for (int c = 0; c < CAMS; c++) {
        #pragma unroll
        for (int p = 0; p < PTS; p++) {
            float x = refx + offq[c*4 + p*2 + 0];
            float y = refy + offq[c*4 + p*2 + 1];
            float a = __shfl_sync(0xffffffffu, e, c*2 + p) * r;
            float x0f = floorf(x), y0f = floorf(y);
            float wx = x - x0f, wy = y - y0f;
            int x0 = (int)x0f, y0 = (int)y0f;
            int x0c = min(max(x0,   0), FW-1);
            int x1c = min(max(x0+1, 0), FW-1);
            int y0c = min(max(y0,   0), FH-1);
            int y1c = min(max(y0+1, 0), FH-1);
            const float* vb = val + (size_t)c*Lf*Dm + h*DHh + lane;
            float v00 = vb[(y0c*FW + x0c)*Dm];
            float v01 = vb[(y0c*FW + x1c)*Dm];
            float v10 = vb[(y1c*FW + x0c)*Dm];
            float v11 = vb[(y1c*FW + x1c)*Dm];
            acc += a * ((1.f-wx)*(1.f-wy)*v00 + wx*(1.f-wy)*v01
                      + (1.f-wx)*wy*v10      + wx*wy*v11);
        }
    }
    agg[(size_t)q*Dm + h*DHh + lane] = acc;
}

// ---------------- residual add + LayerNorm(256) ----------------
__global__ void k_ln_residual(float* __restrict__ q, const float* __restrict__ delta,
                              const float* __restrict__ g, const float* __restrict__ b)
{
    int row = blockIdx.x*8 + threadIdx.y;
    int lane = threadIdx.x;
    size_t base = (size_t)row * Dm;
    float v[8]; float s = 0.f;
    #pragma unroll
    for (int i = 0; i < 8; i++) {
        int d = lane + 32*i;
        v[i] = q[base+d] + delta[base+d];
        s += v[i];
    }
    #pragma unroll
    for (int o = 16; o > 0; o >>= 1) s += __shfl_xor_sync(0xffffffffu, s, o);
    float mean = s * (1.f/256.f);
    float s2 = 0.f;
    #pragma unroll
    for (int i = 0; i < 8; i++) { float d0 = v[i]-mean; s2 += d0*d0; }
    #pragma unroll
    for (int o = 16; o > 0; o >>= 1) s2 += __shfl_xor_sync(0xffffffffu, s2, o);
    float rstd = rsqrtf(s2*(1.f/256.f) + 1e-5f);
    #pragma unroll
    for (int i = 0; i < 8; i++) {
        int d = lane + 32*i;
        q[base+d] = (v[i]-mean)*rstd*g[d] + b[d];
    }
}

// ---------------- q -> vol ----------------
__global__ void k_vol(const float* __restrict__ q, float* __restrict__ vol)
{
    int i = blockIdx.x*blockDim.x + threadIdx.x;
    if (i >= Dm*NSP) return;
    int n = i % NSP, ch = i / NSP;
    int a = n/400, b = (n>>3)%50, c = n&7;
    vol[i] = q[((size_t)((c*50 + b)*50 + a))*Dm + ch];
}

// ---------------- GroupNorm: deterministic 2-stage ----------------
__global__ void k_gn_reduce(const float* __restrict__ x, int gc, int nblk)
{
    int g = blockIdx.x / nblk;
    int b = blockIdx.x % nblk;
    size_t E = (size_t)gc * SP;
    size_t chunk = E / nblk;
    const float4* p = (const float4*)(x + (size_t)g*E + (size_t)b*chunk);
    int n4 = (int)(chunk >> 2);
    float s = 0.f, sq = 0.f;
    for (int i = threadIdx.x; i < n4; i += 256) {
        float4 v = p[i];
        s  += v.x + v.y + v.z + v.w;
        sq += v.x*v.x + v.y*v.y + v.z*v.z + v.w*v.w;
    }
    __shared__ float sh[256], sh2[256];
    sh[threadIdx.x] = s; sh2[threadIdx.x] = sq;
    __syncthreads();
    for (int o = 128; o > 0; o >>= 1) {
        if (threadIdx.x < o) { sh[threadIdx.x] += sh[threadIdx.x+o]; sh2[threadIdx.x] += sh2[threadIdx.x+o]; }
        __syncthreads();
    }
    if (threadIdx.x == 0) { g_psum[blockIdx.x] = sh[0]; g_psq[blockIdx.x] = sh2[0]; }
}

__global__ void k_gn_finalize(int gc, int nblk)
{
    int g = threadIdx.x;
    if (g >= 16) return;
    float s = 0.f, sq = 0.f;
    for (int b = 0; b < nblk; b++) { s += g_psum[g*nblk+b]; sq += g_psq[g*nblk+b]; }
    float E = (float)gc * (float)SP;
    float m = s / E;
    float var = sq / E - m*m;
    g_mean[g] = m;
    g_rstd[g] = rsqrtf(var + 1e-5f);
}

// per-channel GN1 coefficients for fusion into conv3
__global__ void k_gn_coeff(const float* __restrict__ g1, const float* __restrict__ b1)
{
    int ch = threadIdx.x;      // 256
    int g = ch >> 4;
    float sc = g_rstd[g] * g1[ch];
    g_scale[ch] = sc;
    g_shift[ch] = b1[ch] - g_mean[g] * sc;
}

__global__ void k_gn_norm_relu(float* __restrict__ x, const float* __restrict__ gamma,
                               const float* __restrict__ beta, int C, int gc)
{
    int i = blockIdx.x*blockDim.x + threadIdx.x;
    if (i >= C*SP) return;
    int ch = i / SP;
    int g = ch / gc;
    float v = (x[i] - g_mean[g]) * g_rstd[g] * gamma[ch] + beta[ch];
    x[i] = fmaxf(v, 0.f);
}

// ---------------- conv3 weight prepack: [tap][ic][oc], tf32-rounded ----------------
__global__ void k_prepack_w(const float* __restrict__ W, float* __restrict__ Wp)
{
    int i = blockIdx.x*blockDim.x + threadIdx.x;
    if (i >= 27*256*192) return;
    int oc = i % 192;
    int ic = (i / 192) % 256;
    int tap = i / (192*256);
    uint32_t v = f2tf32(W[((size_t)oc*256 + ic)*27 + tap]);
    Wp[i] = __uint_as_float(v);
}

// ---------------- conv3 via mma.sync tf32 (double-buffered, GN1+relu fused) ----------------
// grid (625, 2), 256 threads. CTA: 96 oc x 256 sp, K = 27*256. X is RAW deconv output.
__global__ __launch_bounds__(256, 1)
void k_conv3_mma(const float* __restrict__ X, const float* __restrict__ Wp,
                 const float* __restrict__ scale, const float* __restrict__ shift,
                 float* __restrict__ Out)
{
    __shared__ float As[2][96*17];
    __shared__ float Bs[2][16][260];

    int t = threadIdx.x;
    int wid = t >> 5, l = t & 31;
    int warp_m = wid & 1, warp_n = wid >> 1;
    int qrow = l >> 2, qcol = l & 3;
    int n0 = blockIdx.x * 256;
    int ocb = blockIdx.y * 96;

    int s = n0 + t;
    int w = s & 15, h = (s >> 4) % 100, d = s / 1600;

    int ofsA[6], smA[6];
    #pragma unroll
    for (int i = 0; i < 6; i++) {
        int e = i*256 + t;
        int j = e / 96, m = e % 96;
        ofsA[i] = j*192 + ocb + m;
        smA[i]  = m*17 + j;
    }

    float acc[3][8][4];
    #pragma unroll
    for (int a = 0; a < 3; a++)
        #pragma unroll
        for (int b = 0; b < 8; b++)
            #pragma unroll
            for (int c = 0; c < 4; c++) acc[a][b][c] = 0.f;

    float ldB[16], ldA[6];
    int voff = 0; bool vvalid = false;

    // chunk 0 (tap 0, icc 0)
    {
        int iw = w - 1, ih = h - 1, id = d - 1;
        vvalid = (iw >= 0 && ih >= 0 && id >= 0);
        voff = id*1600 + ih*16 + iw;
        const float* xb = X + (vvalid ? voff : 0);
        #pragma unroll
        for (int j = 0; j < 16; j++) {
            float x = vvalid ? xb[(size_t)j*SP] : 0.f;
            ldB[j] = vvalid ? fmaxf(fmaf(x, __ldg(&scale[j]), __ldg(&shift[j])), 0.f) : 0.f;
        }
        #pragma unroll
        for (int i = 0; i < 6; i++) ldA[i] = Wp[ofsA[i]];
    }
    // store chunk 0 -> buf 0
    #pragma unroll
    for (int j = 0; j < 16; j++)
        Bs[0][j][t] = __uint_as_float(f2tf32(ldB[j]));
    #pragma unroll
    for (int i = 0; i < 6; i++)
        As[0][smA[i]] = ldA[i];
    // load chunk 1 (tap 0, icc 1): validity unchanged
    {
        const float* xb = X + (size_t)16*SP + (vvalid ? voff : 0);
        #pragma unroll
        for (int j = 0; j < 16; j++) {
            float x = vvalid ? xb[(size_t)j*SP] : 0.f;
            ldB[j] = vvalid ? fmaxf(fmaf(x, __ldg(&scale[16+j]), __ldg(&shift[16+j])), 0.f) : 0.f;
        }
        const float* wb = Wp + (size_t)16*192;
        #pragma unroll
        for (int i = 0; i < 6; i++) ldA[i] = wb[ofsA[i]];
    }
    __syncthreads();

    for (int c = 0; c < 432; c++) {
        int cur = c & 1, nxt = cur ^ 1;
        if (c + 1 < 432) {                        // store chunk c+1 into idle buf
            #pragma unroll
            for (int j = 0; j < 16; j++)
                Bs[nxt][j][t] = __uint_as_float(f2tf32(ldB[j]));
            #pragma unroll
            for (int i = 0; i < 6; i++)
                As[nxt][smA[i]] = ldA[i];
        }
        if (c + 2 < 432) {                        // prefetch chunk c+2
            int cn = c + 2;
            int tap = cn >> 4, icc = cn & 15;
            if (icc == 0) {
                int kd = tap/9, kh = (tap%9)/3, kw = tap%3;
                int iw = w + kw - 1, ih = h + kh - 1, id = d + kd - 1;
                vvalid = (iw >= 0 && iw < 16 && ih >= 0 && ih < 100 && id >= 0 && id < 100);
                voff = id*1600 + ih*16 + iw;
            }
            const float* xb = X + (size_t)(icc*16)*SP + (vvalid ? voff : 0);
            #pragma unroll
            for (int j = 0; j < 16; j++) {
                float x = vvalid ? xb[(size_t)j*SP] : 0.f;
                int ch = icc*16 + j;
                ldB[j] = vvalid ? fmaxf(fmaf(x, __ldg(&scale[ch]), __ldg(&shift[ch])), 0.f) : 0.f;
            }
            const float* wb = Wp + ((size_t)tap*256 + icc*16)*192;
            #pragma unroll
            for (int i = 0; i < 6; i++) ldA[i] = wb[ofsA[i]];
        }

        #pragma unroll
        for (int s8 = 0; s8 < 2; s8++) {
            uint32_t af[3][4];
            #pragma unroll
            for (int mt = 0; mt < 3; mt++) {
                int m = warp_m*48 + mt*16;
                int kb = s8*8 + qcol;
                af[mt][0] = __float_as_uint(As[cur][(m+qrow  )*17 + kb    ]);
                af[mt][1] = __float_as_uint(As[cur][(m+qrow+8)*17 + kb    ]);
                af[mt][2] = __float_as_uint(As[cur][(m+qrow  )*17 + kb + 4]);
                af[mt][3] = __float_as_uint(As[cur][(m+qrow+8)*17 + kb + 4]);
            }
            #pragma unroll
            for (int nt = 0; nt < 8; nt++) {
                int n = warp_n*64 + nt*8 + qrow;
                uint32_t b0 = __float_as_uint(Bs[cur][s8*8 + qcol    ][n]);
                uint32_t b1 = __float_as_uint(Bs[cur][s8*8 + qcol + 4][n]);
                #pragma unroll
                for (int mt = 0; mt < 3; mt++)
                    MMA_TF32(acc[mt][nt], af[mt], b0, b1);
            }
        }
        __syncthreads();
    }

    #pragma unroll
    for (int mt = 0; mt < 3; mt++) {
        int oc0 = ocb + warp_m*48 + mt*16 + qrow;
        #pragma unroll
        for (int nt = 0; nt < 8; nt++) {
            int sp = n0 + warp_n*64 + nt*8 + qcol*2;
            *(float2*)&Out[(size_t)oc0*SP + sp]     = make_float2(acc[mt][nt][0], acc[mt][nt][1]);
            *(float2*)&Out[(size_t)(oc0+8)*SP + sp] = make_float2(acc[mt][nt][2], acc[mt][nt][3]);
        }
    }
}

// ---------------- host launcher ----------------
extern "C" void kernel_launch(void* const* d_in, const int* in_sizes, int n_in,
                              void* d_out, int out_size)
{
    const float* camera_x = (const float*)d_in[0];
    const int*   ids      = (const int*)  d_in[1];
    const float* mask_tok = (const float*)d_in[4];
    const float* vol_emb  = (const float*)d_in[5];
    const float* W_tc     = (const float*)d_in[6];
    const float* b_tc     = (const float*)d_in[7];
    const float* cams_e   = (const float*)d_in[8];
    const float* lvl_e    = (const float*)d_in[9];
    const float* W_off    = (const float*)d_in[10];
    const float* b_off    = (const float*)d_in[11];
    const float* W_att    = (const float*)d_in[12];
    const float* b_att    = (const float*)d_in[13];
    const float* W_val    = (const float*)d_in[14];
    const float* b_val    = (const float*)d_in[15];
    const float* W_out    = (const float*)d_in[16];
    const float* b_out    = (const float*)d_in[17];
    const float* ln1g     = (const float*)d_in[18];
    const float* ln1b     = (const float*)d_in[19];
    const float* W_ff1    = (const float*)d_in[20];
    const float* b_ff1    = (const float*)d_in[21];
    const float* W_ff2    = (const float*)d_in[22];
    const float* b_ff2    = (const float*)d_in[23];
    const float* ln2g     = (const float*)d_in[24];
    const float* ln2b     = (const float*)d_in[25];
    const float* deconv_w = (const float*)d_in[26];
    const float* gn1g     = (const float*)d_in[27];
    const float* gn1b     = (const float*)d_in[28];
    const float* conv3_w  = (const float*)d_in[29];
    const float* gn2g     = (const float*)d_in[30];
    const float* gn2b     = (const float*)d_in[31];
    float* out = (float*)d_out;

    float *full,*feat,*valb,*q,*off,*att,*agg,*hid,*delta,*vol,*x1,*wp,*gsc,*gsh;
    cudaGetSymbolAddress((void**)&full,  g_full);
    cudaGetSymbolAddress((void**)&feat,  g_feat);
    cudaGetSymbolAddress((void**)&valb,  g_valb);
    cudaGetSymbolAddress((void**)&q,     g_q);
    cudaGetSymbolAddress((void**)&off,   g_off);
    cudaGetSymbolAddress((void**)&att,   g_att);
    cudaGetSymbolAddress((void**)&agg,   g_agg);
    cudaGetSymbolAddress((void**)&hid,   g_hid);
    cudaGetSymbolAddress((void**)&delta, g_delta);
    cudaGetSymbolAddress((void**)&vol,   g_vol);
    cudaGetSymbolAddress((void**)&x1,    g_x1);
    cudaGetSymbolAddress((void**)&wp,    g_wp);
    cudaGetSymbolAddress((void**)&gsc,   g_scale);
    cudaGetSymbolAddress((void**)&gsh,   g_shift);

    int write_camx = (out_size >= X_ELEMS + CAMX_ELEMS) ? 1 : 0;
    float* camx = out + X_ELEMS;

    // 1) restore + cam_x
    k_build_full<<<(CAMS*Lf*IN_C + 255)/256, 256>>>(camera_x, ids, mask_tok, full, camx, write_camx);

    // 1b) prepack conv3 weights (tf32, [tap][ic][oc])
    k_prepack_w<<<(27*256*192 + 255)/256, 256>>>(conv3_w, wp);

    // 2) feat = relu(full @ W_tc^T + b_tc) + embeds
    k_sgemm_nt<<<dim3(4, 17), 256>>>(full, W_tc, b_tc, feat, CAMS*Lf, Dm, IN_C, 1);
    k_add_embeds<<<(CAMS*Lf*Dm + 255)/256, 256>>>(feat, cams_e, lvl_e);

    // 3) q = vol_emb
    cudaMemcpyAsync(q, vol_emb, sizeof(float)*(size_t)NQ*Dm, cudaMemcpyDeviceToDevice, 0);

    // 4) deformable layers (all big GEMMs on tensor cores; softmax fused into sample)
    for (int l = 0; l < LAYERS; l++) {
        k_sgemm_nn<<<dim3(4, 17),  256>>>(feat, W_val + (size_t)l*Dm*Dm,  b_val + l*Dm,  valb, CAMS*Lf, Dm,  Dm, 0);
        k_gemm_tf32<<<dim3(3, 157), 256>>>(q,   W_off + (size_t)l*Dm*192, b_off + l*192, off,  NQ, 192, Dm, 0);
        k_gemm_tf32<<<dim3(2, 157), 256>>>(q,   W_att + (size_t)l*Dm*96,  b_att + l*96,  att,  NQ, 96,  Dm, 0);
        k_sample<<<NQ, dim3(32, 8)>>>(valb, off, att, agg);
        k_gemm_tf32<<<dim3(4, 157), 256>>>(agg, W_out + (size_t)l*Dm*Dm, b_out + l*Dm, delta, NQ, Dm, Dm, 0);
        k_ln_residual<<<NQ/8, dim3(32, 8)>>>(q, delta, ln1g + l*Dm, ln1b + l*Dm);
        k_gemm_tf32<<<dim3(8, 157), 256>>>(q,   W_ff1 + (size_t)l*Dm*FFNd, b_ff1 + l*FFNd, hid,   NQ, FFNd, Dm,   1);
        k_gemm_tf32<<<dim3(4, 157), 256>>>(hid, W_ff2 + (size_t)l*FFNd*Dm, b_ff2 + l*Dm,   delta, NQ, Dm,   FFNd, 0);
        k_ln_residual<<<NQ/8, dim3(32, 8)>>>(q, delta, ln2g + l*Dm, ln2b + l*Dm);
    }

    // 5) vol
    k_vol<<<(Dm*NSP + 255)/256, 256>>>(q, vol);

    // 6) deconv -> x1 (tf32, double-buffered)
    k_deconv_tf32<<<dim3(313, 2, 8), 256>>>(deconv_w, vol, x1);

    // 7) GN1 stats + fused coefficients (normalize+relu happens inside conv3 load)
    k_gn_reduce<<<16*32, 256>>>(x1, 16, 32);
    k_gn_finalize<<<1, 32>>>(16, 32);
    k_gn_coeff<<<1, 256>>>(gn1g, gn1b);

    // 8) conv3 via mma.sync tf32 (reads raw x1, applies GN1+relu on the fly)
    k_conv3_mma<<<dim3(625, 2), 256>>>(x1, wp, gsc, gsh, out);

    // 9) GN2 + relu
    k_gn_reduce<<<16*32, 256>>>(out, 12, 32);
    k_gn_finalize<<<1, 32>>>(12, 32);
    k_gn_norm_relu<<<(192*SP + 255)/256, 256>>>(out, gn2g, gn2b, 192, 12);
}

// round 13
// speedup vs baseline: 1.0040x; 1.0040x over previous
#include <cuda_runtime.h>
#include <math.h>
#include <stdint.h>

// ---------------- problem constants ----------------
#define CAMS   6
#define HEADS  8
#define PTS    2
#define LAYERS 3
#define Dm     256
#define DHh    32
#define FFNd   512
#define NQ     20000
#define IN_C   768
#define FH     8
#define FW     22
#define Lf     176
#define LVIS   44
#define NSP    20000          // 50*50*8  (deconv input spatial)
#define SP     160000         // 100*100*16 (deconv output spatial)
#define X_ELEMS   (192*SP)
#define CAMX_ELEMS (CAMS*IN_C*Lf)

// ---------------- scratch (static device memory; no allocations) ----------------
__device__ float g_full [CAMS*Lf*IN_C];
__device__ float g_feat [CAMS*Lf*Dm];
__device__ float g_valb [CAMS*Lf*Dm];
__device__ float g_q    [NQ*Dm];
__device__ float g_off  [NQ*HEADS*CAMS*PTS*2];
__device__ float g_att  [NQ*HEADS*CAMS*PTS];
__device__ float g_agg  [NQ*Dm];
__device__ float g_hid  [NQ*FFNd];
__device__ float g_delta[NQ*Dm];
__device__ float g_vol  [Dm*NSP];
__device__ float g_x1   [Dm*SP];
__device__ float g_wp   [27*256*192];      // conv3 weights prepacked [tap][ic][oc], tf32
__device__ float g_psum [1024];
__device__ float g_psq  [1024];
__device__ float g_mean [16];
__device__ float g_rstd [16];
__device__ float g_scale[256];             // GN1 fused per-channel scale
__device__ float g_shift[256];             // GN1 fused per-channel shift

__device__ __forceinline__ uint32_t f2tf32(float v) {
    uint32_t o;
    asm("cvt.rna.tf32.f32 %0, %1;" : "=r"(o) : "f"(v));
    return o;
}
#define MMA_TF32(acc, af, b0, b1) \
    asm volatile( \
        "mma.sync.aligned.m16n8k8.row.col.f32.tf32.tf32.f32 " \
        "{%0,%1,%2,%3}, {%4,%5,%6,%7}, {%8,%9}, {%0,%1,%2,%3};" \
        : "+f"((acc)[0]), "+f"((acc)[1]), "+f"((acc)[2]), "+f"((acc)[3]) \
        : "r"((af)[0]), "r"((af)[1]), "r"((af)[2]), "r"((af)[3]), \
          "r"(b0), "r"(b1))

// ---------------- kernel 1: restore full tokens + emit cam_x ----------------
__global__ void k_build_full(const float* __restrict__ cx, const int* __restrict__ ids,
                             const float* __restrict__ mt, float* __restrict__ full,
                             float* __restrict__ camx, int write_camx)
{
    int i = blockIdx.x * blockDim.x + threadIdx.x;
    if (i >= CAMS*Lf*IN_C) return;
    int c = i % IN_C;
    int l = (i / IN_C) % Lf;
    int n = i / (IN_C*Lf);
    int id = ids[n*Lf + l];
    float v = (id < LVIS) ? cx[((size_t)n*LVIS + id)*IN_C + c] : mt[c];
    full[i] = v;
    if (write_camx)
        camx[((size_t)n*IN_C + c)*Lf + l] = v;
}

// ---------------- generic tiled SGEMM: C = A(MxK) * B(KxN) ----------------
__global__ __launch_bounds__(256)
void k_sgemm_nn(const float* __restrict__ A, const float* __restrict__ B,
                const float* __restrict__ bias, float* __restrict__ C,
                int M, int N, int K, int relu)
{
    __shared__ float As[16][64];
    __shared__ float Bs[16][68];
    int m0 = blockIdx.y * 64, n0 = blockIdx.x * 64;
    int t = threadIdx.x, ty = t >> 4, tx = t & 15;
    float acc[4][4] = {};
    int am = t >> 2, ak = (t & 3) << 2;
    int bk = ty,     bn = tx << 2;

    for (int k0 = 0; k0 < K; k0 += 16) {
        float4 av = make_float4(0.f,0.f,0.f,0.f);
        if (m0 + am < M) av = *(const float4*)(A + (size_t)(m0+am)*K + k0 + ak);
        As[ak+0][am] = av.x; As[ak+1][am] = av.y; As[ak+2][am] = av.z; As[ak+3][am] = av.w;
        float4 bv = make_float4(0.f,0.f,0.f,0.f);
        if (n0 + bn < N) bv = *(const float4*)(B + (size_t)(k0+bk)*N + n0 + bn);
        *(float4*)&Bs[bk][bn] = bv;
        __syncthreads();
        #pragma unroll
        for (int kk = 0; kk < 16; kk++) {
            float4 a = *(const float4*)&As[kk][ty<<2];
            float4 b = *(const float4*)&Bs[kk][tx<<2];
            float av4[4] = {a.x,a.y,a.z,a.w};
            float bv4[4] = {b.x,b.y,b.z,b.w};
            #pragma unroll
            for (int i = 0; i < 4; i++)
                #pragma unroll
                for (int j = 0; j < 4; j++)
                    acc[i][j] += av4[i]*bv4[j];
        }
        __syncthreads();
    }
    #pragma unroll
    for (int i = 0; i < 4; i++) {
        int m = m0 + (ty<<2) + i;
        if (m >= M) continue;
        #pragma unroll
        for (int j = 0; j < 4; j++) {
            int n = n0 + (tx<<2) + j;
            if (n >= N) continue;
            float v = acc[i][j] + (bias ? bias[n] : 0.f);
            if (relu) v = fmaxf(v, 0.f);
            C[(size_t)m*N + n] = v;
        }
    }
}

// ---------------- SGEMM with B transposed ----------------
__global__ __launch_bounds__(256)
void k_sgemm_nt(const float* __restrict__ A, const float* __restrict__ B,
                const float* __restrict__ bias, float* __restrict__ C,
                int M, int N, int K, int relu)
{
    __shared__ float As[16][64];
    __shared__ float Bs[16][68];
    int m0 = blockIdx.y * 64, n0 = blockIdx.x * 64;
    int t = threadIdx.x, ty = t >> 4, tx = t & 15;
    float acc[4][4] = {};
    int lr = t >> 2, lk = (t & 3) << 2;

    for (int k0 = 0; k0 < K; k0 += 16) {
        float4 av = make_float4(0.f,0.f,0.f,0.f);
        if (m0 + lr < M) av = *(const float4*)(A + (size_t)(m0+lr)*K + k0 + lk);
        As[lk+0][lr] = av.x; As[lk+1][lr] = av.y; As[lk+2][lr] = av.z; As[lk+3][lr] = av.w;
        float4 bv = make_float4(0.f,0.f,0.f,0.f);
        if (n0 + lr < N) bv = *(const float4*)(B + (size_t)(n0+lr)*K + k0 + lk);
        Bs[lk+0][lr] = bv.x; Bs[lk+1][lr] = bv.y; Bs[lk+2][lr] = bv.z; Bs[lk+3][lr] = bv.w;
        __syncthreads();
        #pragma unroll
        for (int kk = 0; kk < 16; kk++) {
            float4 a = *(const float4*)&As[kk][ty<<2];
            float4 b = *(const float4*)&Bs[kk][tx<<2];
            float av4[4] = {a.x,a.y,a.z,a.w};
            float bv4[4] = {b.x,b.y,b.z,b.w};
            #pragma unroll
            for (int i = 0; i < 4; i++)
                #pragma unroll
                for (int j = 0; j < 4; j++)
                    acc[i][j] += av4[i]*bv4[j];
        }
        __syncthreads();
    }
    #pragma unroll
    for (int i = 0; i < 4; i++) {
        int m = m0 + (ty<<2) + i;
        if (m >= M) continue;
        #pragma unroll
        for (int j = 0; j < 4; j++) {
            int n = n0 + (tx<<2) + j;
            if (n >= N) continue;
            float v = acc[i][j] + (bias ? bias[n] : 0.f);
            if (relu) v = fmaxf(v, 0.f);
            C[(size_t)m*N + n] = v;
        }
    }
}

// ---------------- tf32 mma GEMM (single-buffered, R9 structure) ----------------
// CTA 128M x 64N, 8 warps = 4(m) x 2(n), warp tile 32x32 = 2x4 m16n8k8.
__global__ __launch_bounds__(256)
void k_gemm_tf32(const float* __restrict__ A, const float* __restrict__ B,
                 const float* __restrict__ bias, float* __restrict__ C,
                 int M, int N, int K, int relu)
{
    __shared__ float As[128*17];     // [m][k], stride 17
    __shared__ float Bs[16][68];     // [k][n]
    int t = threadIdx.x;
    int wid = t >> 5, l = t & 31;
    int warp_m = wid & 3, warp_n = wid >> 2;
    int qrow = l >> 2, qcol = l & 3;
    int m0 = blockIdx.y * 128, n0 = blockIdx.x * 64;

    float acc[2][4][4];
    #pragma unroll
    for (int a = 0; a < 2; a++)
        #pragma unroll
        for (int b = 0; b < 4; b++)
            #pragma unroll
            for (int c = 0; c < 4; c++) acc[a][b][c] = 0.f;

    float ldA[8], ldB[4];
    #pragma unroll
    for (int i = 0; i < 8; i++) {
        int e = i*256 + t, m = e >> 4, k = e & 15;
        ldA[i] = (m0 + m < M) ? A[(size_t)(m0+m)*K + k] : 0.f;
    }
    #pragma unroll
    for (int i = 0; i < 4; i++) {
        int e = i*256 + t, k = e >> 6, n = e & 63;
        ldB[i] = (n0 + n < N) ? B[(size_t)k*N + n0 + n] : 0.f;
    }

    int nk = K >> 4;
    for (int c = 0; c < nk; c++) {
        #pragma unroll
        for (int i = 0; i < 8; i++) {
            int e = i*256 + t, m = e >> 4, k = e & 15;
            As[m*17 + k] = __uint_as_float(f2tf32(ldA[i]));
        }
        #pragma unroll
        for (int i = 0; i < 4; i++) {
            int e = i*256 + t, k = e >> 6, n = e & 63;
            Bs[k][n] = __uint_as_float(f2tf32(ldB[i]));
        }
        __syncthreads();
        if (c + 1 < nk) {
            int k0 = (c + 1) << 4;
            #pragma unroll
            for (int i = 0; i < 8; i++) {
                int e = i*256 + t, m = e >> 4, k = e & 15;
                ldA[i] = (m0 + m < M) ? A[(size_t)(m0+m)*K + k0 + k] : 0.f;
            }
            #pragma unroll
            for (int i = 0; i < 4; i++) {
                int e = i*256 + t, k = e >> 6, n = e & 63;
                ldB[i] = (n0 + n < N) ? B[(size_t)(k0+k)*N + n0 + n] : 0.f;
            }
        }
        #pragma unroll
        for (int s8 = 0; s8 < 2; s8++) {
            uint32_t af[2][4];
            #pragma unroll
            for (int mt = 0; mt < 2; mt++) {
                int m = warp_m*32 + mt*16;
                int kb = s8*8 + qcol;
                af[mt][0] = __float_as_uint(As[(m+qrow  )*17 + kb    ]);
                af[mt][1] = __float_as_uint(As[(m+qrow+8)*17 + kb    ]);
                af[mt][2] = __float_as_uint(As[(m+qrow  )*17 + kb + 4]);
                af[mt][3] = __float_as_uint(As[(m+qrow+8)*17 + kb + 4]);
            }
            #pragma unroll
            for (int nt = 0; nt < 4; nt++) {
                int n = warp_n*32 + nt*8 + qrow;
                uint32_t b0 = __float_as_uint(Bs[s8*8 + qcol    ][n]);
                uint32_t b1 = __float_as_uint(Bs[s8*8 + qcol + 4][n]);
                #pragma unroll
                for (int mt = 0; mt < 2; mt++)
                    MMA_TF32(acc[mt][nt], af[mt], b0, b1);
            }
        }
        __syncthreads();
    }

    #pragma unroll
    for (int mt = 0; mt < 2; mt++) {
        int mrow = m0 + warp_m*32 + mt*16 + qrow;
        #pragma unroll
        for (int nt = 0; nt < 4; nt++) {
            int n = n0 + warp_n*32 + nt*8 + qcol*2;
            if (n >= N) continue;
            float b0v = bias ? bias[n]   : 0.f;
            float b1v = bias ? bias[n+1] : 0.f;
            float v0 = acc[mt][nt][0] + b0v, v1 = acc[mt][nt][1] + b1v;
            float v2 = acc[mt][nt][2] + b0v, v3 = acc[mt][nt][3] + b1v;
            if (relu) { v0=fmaxf(v0,0.f); v1=fmaxf(v1,0.f); v2=fmaxf(v2,0.f); v3=fmaxf(v3,0.f); }
            if (mrow < M)     *(float2*)&C[(size_t)mrow*N + n]     = make_float2(v0, v1);
            if (mrow + 8 < M) *(float2*)&C[(size_t)(mrow+8)*N + n] = make_float2(v2, v3);
        }
    }
}

// ---------------- deconv via tf32 mma (single-buffered, R9 structure) ----------------
// grid (313, 2, 8). CTA 128 oc x 64 sp. Wd layout [oc][ic][tap] (stride 8).
__global__ __launch_bounds__(256)
void k_deconv_tf32(const float* __restrict__ Wd, const float* __restrict__ V,
                   float* __restrict__ X1)
{
    __shared__ float As[128*17];
    __shared__ float Bs[16][68];
    int t = threadIdx.x;
    int wid = t >> 5, l = t & 31;
    int warp_m = wid & 3, warp_n = wid >> 2;
    int qrow = l >> 2, qcol = l & 3;
    int m0 = blockIdx.y * 128, n0 = blockIdx.x * 64;
    int tap = blockIdx.z;
    int k1 = tap>>2, k2 = (tap>>1)&1, k3 = tap&1;

    float acc[2][4][4];
    #pragma unroll
    for (int a = 0; a < 2; a++)
        #pragma unroll
        for (int b = 0; b < 4; b++)
            #pragma unroll
            for (int c = 0; c < 4; c++) acc[a][b][c] = 0.f;

    float ldA[8], ldB[4];
    #pragma unroll
    for (int i = 0; i < 8; i++) {
        int e = i*256 + t, m = e >> 4, k = e & 15;
        ldA[i] = Wd[(((size_t)(m0+m))*256 + k)*8 + tap];
    }
    #pragma unroll
    for (int i = 0; i < 4; i++) {
        int e = i*256 + t, k = e >> 6, n = e & 63;
        ldB[i] = (n0 + n < NSP) ? V[(size_t)k*NSP + n0 + n] : 0.f;
    }

    for (int c = 0; c < 16; c++) {       // K = 256
        #pragma unroll
        for (int i = 0; i < 8; i++) {
            int e = i*256 + t, m = e >> 4, k = e & 15;
            As[m*17 + k] = __uint_as_float(f2tf32(ldA[i]));
        }
        #pragma unroll
        for (int i = 0; i < 4; i++) {
            int e = i*256 + t, k = e >> 6, n = e & 63;
            Bs[k][n] = __uint_as_float(f2tf32(ldB[i]));
        }
        __syncthreads();
        if (c + 1 < 16) {
            int k0 = (c + 1) << 4;
            #pragma unroll
            for (int i = 0; i < 8; i++) {
                int e = i*256 + t, m = e >> 4, k = e & 15;
                ldA[i] = Wd[(((size_t)(m0+m))*256 + k0 + k)*8 + tap];
            }
            #pragma unroll
            for (int i = 0; i < 4; i++) {
                int e = i*256 + t, k = e >> 6, n = e & 63;
                ldB[i] = (n0 + n < NSP) ? V[(size_t)(k0+k)*NSP + n0 + n] : 0.f;
            }
        }
        #pragma unroll
        for (int s8 = 0; s8 < 2; s8++) {
            uint32_t af[2][4];
            #pragma unroll
            for (int mt = 0; mt < 2; mt++) {
                int m = warp_m*32 + mt*16;
                int kb = s8*8 + qcol;
                af[mt][0] = __float_as_uint(As[(m+qrow  )*17 + kb    ]);
                af[mt][1] = __float_as_uint(As[(m+qrow+8)*17 + kb    ]);
                af[mt][2] = __float_as_uint(As[(m+qrow  )*17 + kb + 4]);
                af[mt][3] = __float_as_uint(As[(m+qrow+8)*17 + kb + 4]);
            }
            #pragma unroll
            for (int nt = 0; nt < 4; nt++) {
                int n = warp_n*32 + nt*8 + qrow;
                uint32_t b0 = __float_as_uint(Bs[s8*8 + qcol    ][n]);
                uint32_t b1 = __float_as_uint(Bs[s8*8 + qcol + 4][n]);
                #pragma unroll
                for (int mt = 0; mt < 2; mt++)
                    MMA_TF32(acc[mt][nt], af[mt], b0, b1);
            }
        }
        __syncthreads();
    }

    // scatter epilogue: column n -> (od,oh,ow) parity position
    #pragma unroll
    for (int mt = 0; mt < 2; mt++) {
        int mrow = m0 + warp_m*32 + mt*16 + qrow;
        #pragma unroll
        for (int nt = 0; nt < 4; nt++) {
            int n = n0 + warp_n*32 + nt*8 + qcol*2;
            #pragma unroll
            for (int j = 0; j < 2; j++) {
                int col = n + j;
                if (col >= NSP) continue;
                int a_ = col/400, b_ = (col>>3)%50, c_ = col&7;
                size_t o = (size_t)(2*a_ + 1 - k1)*1600 + (2*b_ + 1 - k2)*16 + (2*c_ + 1 - k3);
                X1[(size_t)mrow*SP + o]     = acc[mt][nt][j];
                X1[(size_t)(mrow+8)*SP + o] = acc[mt][nt][2+j];
            }
        }
    }
}

// ---------------- feat += cams_embeds[cam] + level_embeds ----------------
__global__ void k_add_embeds(float* __restrict__ feat, const float* __restrict__ cams,
                             const float* __restrict__ lvl)
{
    int i = blockIdx.x * blockDim.x + threadIdx.x;
    if (i >= CAMS*Lf*Dm) return;
    int d = i % Dm;
    int n = i / (Lf*Dm);
    feat[i] += cams[n*Dm + d] + lvl[d];
}

// ---------------- deformable sampling with fused softmax ----------------
__global__ void k_sample(const float* __restrict__ val, const float* __restrict__ off,
                         const float* __restrict__ att, float* __restrict__ agg)
{
    int q = blockIdx.x;
    int h = threadIdx.y;
    int lane = threadIdx.x;
    float refx = ((float)(q % 50) + 0.5f) * (22.f/50.f) - 0.5f;
    float refy = ((float)((q/50) % 50) + 0.5f) * (8.f/50.f) - 0.5f;
    const float* offq = off + (size_t)q*192 + h*24;
    const float* attq = att + (size_t)q*96  + h*12;

    // warp-cooperative softmax over the 12 logits (one warp per head)
    float lg = (lane < 12) ? attq[lane] : -1e30f;
    float mx = lg;
    #pragma unroll
    for (int o = 16; o > 0; o >>= 1) mx = fmaxf(mx, __shfl_xor_sync(0xffffffffu, mx, o));
    float e = (lane < 12) ? expf(lg - mx) : 0.f;
    float ssum = e;
    #pragma unroll
    for (int o = 16; o > 0; o >>= 1) ssum += __shfl_xor_sync(0xffffffffu, ssum, o);
    float r = 1.f / ssum;

    float acc = 0.f;
    #pragma unroll
    for (int c = 0; c < CAMS; c++) {
        #pragma unroll
        for (int p = 0; p < PTS; p++) {
            float x = refx + offq[c*4 + p*2 + 0];
            float y = refy + offq[c*4 + p*2 + 1];
            float a = __shfl_sync(0xffffffffu, e, c*2 + p) * r;
            float x0f = floorf(x), y0f = floorf(y);
            float wx = x - x0f, wy = y - y0f;
            int x0 = (int)x0f, y0 = (int)y0f;
            int x0c = min(max(x0,   0), FW-1);
            int x1c = min(max(x0+1, 0), FW-1);
            int y0c = min(max(y0,   0), FH-1);
            int y1c = min(max(y0+1, 0), FH-1);
            const float* vb = val + (size_t)c*Lf*Dm + h*DHh + lane;
            float v00 = vb[(y0c*FW + x0c)*Dm];
            float v01 = vb[(y0c*FW + x1c)*Dm];
            float v10 = vb[(y1c*FW + x0c)*Dm];
            float v11 = vb[(y1c*FW + x1c)*Dm];
            acc += a * ((1.f-wx)*(1.f-wy)*v00 + wx*(1.f-wy)*v01
                      + (1.f-wx)*wy*v10      + wx*wy*v11);
        }
    }
    agg[(size_t)q*Dm + h*DHh + lane] = acc;
}

// ---------------- residual add + LayerNorm(256) ----------------
__global__ void k_ln_residual(float* __restrict__ q, const float* __restrict__ delta,
                              const float* __restrict__ g, const float* __restrict__ b)
{
    int row = blockIdx.x*8 + threadIdx.y;
    int lane = threadIdx.x;
    size_t base = (size_t)row * Dm;
    float v[8]; float s = 0.f;
    #pragma unroll
    for (int i = 0; i < 8; i++) {
        int d = lane + 32*i;
        v[i] = q[base+d] + delta[base+d];
        s += v[i];
    }
    #pragma unroll
    for (int o = 16; o > 0; o >>= 1) s += __shfl_xor_sync(0xffffffffu, s, o);
    float mean = s * (1.f/256.f);
    float s2 = 0.f;
    #pragma unroll
    for (int i = 0; i < 8; i++) { float d0 = v[i]-mean; s2 += d0*d0; }
    #pragma unroll
    for (int o = 16; o > 0; o >>= 1) s2 += __shfl_xor_sync(0xffffffffu, s2, o);
    float rstd = rsqrtf(s2*(1.f/256.f) + 1e-5f);
    #pragma unroll
    for (int i = 0; i < 8; i++) {
        int d = lane + 32*i;
        q[base+d] = (v[i]-mean)*rstd*g[d] + b[d];
    }
}

// ---------------- q -> vol ----------------
__global__ void k_vol(const float* __restrict__ q, float* __restrict__ vol)
{
    int i = blockIdx.x*blockDim.x + threadIdx.x;
    if (i >= Dm*NSP) return;
    int n = i % NSP, ch = i / NSP;
    int a = n/400, b = (n>>3)%50, c = n&7;
    vol[i] = q[((size_t)((c*50 + b)*50 + a))*Dm + ch];
}

// ---------------- GroupNorm: deterministic 2-stage ----------------
__global__ void k_gn_reduce(const float* __restrict__ x, int gc, int nblk)
{
    int g = blockIdx.x / nblk;
    int b = blockIdx.x % nblk;
    size_t E = (size_t)gc * SP;
    size_t chunk = E / nblk;
    const float4* p = (const float4*)(x + (size_t)g*E + (size_t)b*chunk);
    int n4 = (int)(chunk >> 2);
    float s = 0.f, sq = 0.f;
    for (int i = threadIdx.x; i < n4; i += 256) {
        float4 v = p[i];
        s  += v.x + v.y + v.z + v.w;
        sq += v.x*v.x + v.y*v.y + v.z*v.z + v.w*v.w;
    }
    __shared__ float sh[256], sh2[256];
    sh[threadIdx.x] = s; sh2[threadIdx.x] = sq;
    __syncthreads();
    for (int o = 128; o > 0; o >>= 1) {
        if (threadIdx.x < o) { sh[threadIdx.x] += sh[threadIdx.x+o]; sh2[threadIdx.x] += sh2[threadIdx.x+o]; }
        __syncthreads();
    }
    if (threadIdx.x == 0) { g_psum[blockIdx.x] = sh[0]; g_psq[blockIdx.x] = sh2[0]; }
}

__global__ void k_gn_finalize(int gc, int nblk)
{
    int g = threadIdx.x;
    if (g >= 16) return;
    float s = 0.f, sq = 0.f;
    for (int b = 0; b < nblk; b++) { s += g_psum[g*nblk+b]; sq += g_psq[g*nblk+b]; }
    float E = (float)gc * (float)SP;
    float m = s / E;
    float var = sq / E - m*m;
    g_mean[g] = m;
    g_rstd[g] = rsqrtf(var + 1e-5f);
}

// per-channel GN1 coefficients for fusion into conv3
__global__ void k_gn_coeff(const float* __restrict__ g1, const float* __restrict__ b1)
{
    int ch = threadIdx.x;      // 256
    int g = ch >> 4;
    float sc = g_rstd[g] * g1[ch];
    g_scale[ch] = sc;
    g_shift[ch] = b1[ch] - g_mean[g] * sc;
}

__global__ void k_gn_norm_relu(float* __restrict__ x, const float* __restrict__ gamma,
                               const float* __restrict__ beta, int C, int gc)
{
    int i = blockIdx.x*blockDim.x + threadIdx.x;
    if (i >= C*SP) return;
    int ch = i / SP;
    int g = ch / gc;
    float v = (x[i] - g_mean[g]) * g_rstd[g] * gamma[ch] + beta[ch];
    x[i] = fmaxf(v, 0.f);
}

// ---------------- conv3 weight prepack: [tap][ic][oc], tf32-rounded ----------------
__global__ void k_prepack_w(const float* __restrict__ W, float* __restrict__ Wp)
{
    int i = blockIdx.x*blockDim.x + threadIdx.x;
    if (i >= 27*256*192) return;
    int oc = i % 192;
    int ic = (i / 192) % 256;
    int tap = i / (192*256);
    uint32_t v = f2tf32(W[((size_t)oc*256 + ic)*27 + tap]);
    Wp[i] = __uint_as_float(v);
}

// ---------------- conv3 via mma.sync tf32 (single-buffered, GN1+relu fused on load) ----------------
// grid (625, 2), 256 threads. CTA tile: 96 oc x 256 sp, K = 27*256. X is RAW deconv output.
__global__ __launch_bounds__(256, 1)
void k_conv3_mma(const float* __restrict__ X, const float* __restrict__ Wp,
                 const float* __restrict__ scale, const float* __restrict__ shift,
                 float* __restrict__ Out)
{
    __shared__ float As[96*17];
    __shared__ float Bs[16][260];

    int t = threadIdx.x;
    int wid = t >> 5, l = t & 31;
    int warp_m = wid & 1, warp_n = wid >> 1;
    int qrow = l >> 2, qcol = l & 3;
    int n0 = blockIdx.x * 256;
    int ocb = blockIdx.y * 96;

    int s = n0 + t;
    int w = s & 15, h = (s >> 4) % 100, d = s / 1600;

    int ofsA[6], smA[6];
    #pragma unroll
    for (int i = 0; i < 6; i++) {
        int e = i*256 + t;
        int j = e / 96, m = e % 96;
        ofsA[i] = j*192 + ocb + m;
        smA[i]  = m*17 + j;
    }

    float acc[3][8][4];
    #pragma unroll
    for (int a = 0; a < 3; a++)
        #pragma unroll
        for (int b = 0; b < 8; b++)
            #pragma unroll
            for (int c = 0; c < 4; c++) acc[a][b][c] = 0.f;

    float ldB[16], ldA[6];
    int voff = 0; bool vvalid = false;

    // prologue: load chunk 0 (tap 0: only lower-bound check needed)
    {
        int iw = w - 1, ih = h - 1, id = d - 1;
        vvalid = (iw >= 0 && ih >= 0 && id >= 0);
        voff = id*1600 + ih*16 + iw;
        const float* xb = X + (vvalid ? voff : 0);
        #pragma unroll
        for (int j = 0; j < 16; j++) {
            float x = vvalid ? xb[(size_t)j*SP] : 0.f;
            ldB[j] = vvalid ? fmaxf(fmaf(x, __ldg(&scale[j]), __ldg(&shift[j])), 0.f) : 0.f;
        }
        #pragma unroll
        for (int i = 0; i < 6; i++) ldA[i] = Wp[ofsA[i]];
    }

    for (int c = 0; c < 432; c++) {
        #pragma unroll
        for (int j = 0; j < 16; j++)
            Bs[j][t] = __uint_as_float(f2tf32(ldB[j]));
        #pragma unroll
        for (int i = 0; i < 6; i++)
            As[smA[i]] = ldA[i];
        __syncthreads();

        if (c + 1 < 432) {
            int cn = c + 1;
            int tap = cn >> 4, icc = cn & 15;
            if (icc == 0) {
                int kd = tap/9, kh = (tap%9)/3, kw = tap%3;
                int iw = w + kw - 1, ih = h + kh - 1, id = d + kd - 1;
                vvalid = (iw >= 0 && iw < 16 && ih >= 0 && ih < 100 && id >= 0 && id < 100);
                voff = id*1600 + ih*16 + iw;
            }
            const float* xb = X + (size_t)(icc*16)*SP + (vvalid ? voff : 0);
            #pragma unroll
            for (int j = 0; j < 16; j++) {
                float x = vvalid ? xb[(size_t)j*SP] : 0.f;
                int ch = icc*16 + j;
                ldB[j] = vvalid ? fmaxf(fmaf(x, __ldg(&scale[ch]), __ldg(&shift[ch])), 0.f) : 0.f;
            }
            const float* wb = Wp + ((size_t)tap*256 + icc*16)*192;
            #pragma unroll
            for (int i = 0; i < 6; i++) ldA[i] = wb[ofsA[i]];
        }

        #pragma unroll
        for (int s8 = 0; s8 < 2; s8++) {
            uint32_t af[3][4];
            #pragma unroll
            for (int mt = 0; mt < 3; mt++) {
                int m = warp_m*48 + mt*16;
                int kb = s8*8 + qcol;
                af[mt][0] = __float_as_uint(As[(m+qrow  )*17 + kb    ]);
                af[mt][1] = __float_as_uint(As[(m+qrow+8)*17 + kb    ]);
                af[mt][2] = __float_as_uint(As[(m+qrow  )*17 + kb + 4]);
                af[mt][3] = __float_as_uint(As[(m+qrow+8)*17 + kb + 4]);
            }
            #pragma unroll
            for (int nt = 0; nt < 8; nt++) {
                int n = warp_n*64 + nt*8 + qrow;
                uint32_t b0 = __float_as_uint(Bs[s8*8 + qcol    ][n]);
                uint32_t b1 = __float_as_uint(Bs[s8*8 + qcol + 4][n]);
                #pragma unroll
                for (int mt = 0; mt < 3; mt++)
                    MMA_TF32(acc[mt][nt], af[mt], b0, b1);
            }
        }
        __syncthreads();
    }

    #pragma unroll
    for (int mt = 0; mt < 3; mt++) {
        int oc0 = ocb + warp_m*48 + mt*16 + qrow;
        #pragma unroll
        for (int nt = 0; nt < 8; nt++) {
            int sp = n0 + warp_n*64 + nt*8 + qcol*2;
            *(float2*)&Out[(size_t)oc0*SP + sp]     = make_float2(acc[mt][nt][0], acc[mt][nt][1]);
            *(float2*)&Out[(size_t)(oc0+8)*SP + sp] = make_float2(acc[mt][nt][2], acc[mt][nt][3]);
        }
    }
}

// ---------------- host launcher ----------------
extern "C" void kernel_launch(void* const* d_in, const int* in_sizes, int n_in,
                              void* d_out, int out_size)
{
    const float* camera_x = (const float*)d_in[0];
    const int*   ids      = (const int*)  d_in[1];
    const float* mask_tok = (const float*)d_in[4];
    const float* vol_emb  = (const float*)d_in[5];
    const float* W_tc     = (const float*)d_in[6];
    const float* b_tc     = (const float*)d_in[7];
    const float* cams_e   = (const float*)d_in[8];
    const float* lvl_e    = (const float*)d_in[9];
    const float* W_off    = (const float*)d_in[10];
    const float* b_off    = (const float*)d_in[11];
    const float* W_att    = (const float*)d_in[12];
    const float* b_att    = (const float*)d_in[13];
    const float* W_val    = (const float*)d_in[14];
    const float* b_val    = (const float*)d_in[15];
    const float* W_out    = (const float*)d_in[16];
    const float* b_out    = (const float*)d_in[17];
    const float* ln1g     = (const float*)d_in[18];
    const float* ln1b     = (const float*)d_in[19];
    const float* W_ff1    = (const float*)d_in[20];
    const float* b_ff1    = (const float*)d_in[21];
    const float* W_ff2    = (const float*)d_in[22];
    const float* b_ff2    = (const float*)d_in[23];
    const float* ln2g     = (const float*)d_in[24];
    const float* ln2b     = (const float*)d_in[25];
    const float* deconv_w = (const float*)d_in[26];
    const float* gn1g     = (const float*)d_in[27];
    const float* gn1b     = (const float*)d_in[28];
    const float* conv3_w  = (const float*)d_in[29];
    const float* gn2g     = (const float*)d_in[30];
    const float* gn2b     = (const float*)d_in[31];
    float* out = (float*)d_out;

    float *full,*feat,*valb,*q,*off,*att,*agg,*hid,*delta,*vol,*x1,*wp,*gsc,*gsh;
    cudaGetSymbolAddress((void**)&full,  g_full);
    cudaGetSymbolAddress((void**)&feat,  g_feat);
    cudaGetSymbolAddress((void**)&valb,  g_valb);
    cudaGetSymbolAddress((void**)&q,     g_q);
    cudaGetSymbolAddress((void**)&off,   g_off);
    cudaGetSymbolAddress((void**)&att,   g_att);
    cudaGetSymbolAddress((void**)&agg,   g_agg);
    cudaGetSymbolAddress((void**)&hid,   g_hid);
    cudaGetSymbolAddress((void**)&delta, g_delta);
    cudaGetSymbolAddress((void**)&vol,   g_vol);
    cudaGetSymbolAddress((void**)&x1,    g_x1);
    cudaGetSymbolAddress((void**)&wp,    g_wp);
    cudaGetSymbolAddress((void**)&gsc,   g_scale);
    cudaGetSymbolAddress((void**)&gsh,   g_shift);

    int write_camx = (out_size >= X_ELEMS + CAMX_ELEMS) ? 1 : 0;
    float* camx = out + X_ELEMS;

    // 1) restore + cam_x
    k_build_full<<<(CAMS*Lf*IN_C + 255)/256, 256>>>(camera_x, ids, mask_tok, full, camx, write_camx);

    // 1b) prepack conv3 weights (tf32, [tap][ic][oc])
    k_prepack_w<<<(27*256*192 + 255)/256, 256>>>(conv3_w, wp);

    // 2) feat = relu(full @ W_tc^T + b_tc) + embeds
    k_sgemm_nt<<<dim3(4, 17), 256>>>(full, W_tc, b_tc, feat, CAMS*Lf, Dm, IN_C, 1);
    k_add_embeds<<<(CAMS*Lf*Dm + 255)/256, 256>>>(feat, cams_e, lvl_e);

    // 3) q = vol_emb
    cudaMemcpyAsync(q, vol_emb, sizeof(float)*(size_t)NQ*Dm, cudaMemcpyDeviceToDevice, 0);

    // 4) deformable layers (all big GEMMs on tensor cores; softmax fused into sample)
    for (int l = 0; l < LAYERS; l++) {
        k_sgemm_nn<<<dim3(4, 17),  256>>>(feat, W_val + (size_t)l*Dm*Dm,  b_val + l*Dm,  valb, CAMS*Lf, Dm,  Dm, 0);
        k_gemm_tf32<<<dim3(3, 157), 256>>>(q,   W_off + (size_t)l*Dm*192, b_off + l*192, off,  NQ, 192, Dm, 0);
        k_gemm_tf32<<<dim3(2, 157), 256>>>(q,   W_att + (size_t)l*Dm*96,  b_att + l*96,  att,  NQ, 96,  Dm, 0);
        k_sample<<<NQ, dim3(32, 8)>>>(valb, off, att, agg);
        k_gemm_tf32<<<dim3(4, 157), 256>>>(agg, W_out + (size_t)l*Dm*Dm, b_out + l*Dm, delta, NQ, Dm, Dm, 0);
        k_ln_residual<<<NQ/8, dim3(32, 8)>>>(q, delta, ln1g + l*Dm, ln1b + l*Dm);
        k_gemm_tf32<<<dim3(8, 157), 256>>>(q,   W_ff1 + (size_t)l*Dm*FFNd, b_ff1 + l*FFNd, hid,   NQ, FFNd, Dm,   1);
        k_gemm_tf32<<<dim3(4, 157), 256>>>(hid, W_ff2 + (size_t)l*FFNd*Dm, b_ff2 + l*Dm,   delta, NQ, Dm,   FFNd, 0);
        k_ln_residual<<<NQ/8, dim3(32, 8)>>>(q, delta, ln2g + l*Dm, ln2b + l*Dm);
    }

    // 5) vol
    k_vol<<<(Dm*NSP + 255)/256, 256>>>(q, vol);

    // 6) deconv -> x1 (tf32, single-buffered)
    k_deconv_tf32<<<dim3(313, 2, 8), 256>>>(deconv_w, vol, x1);

    // 7) GN1 stats + fused coefficients (normalize+relu happens inside conv3 load)
    k_gn_reduce<<<16*32, 256>>>(x1, 16, 32);
    k_gn_finalize<<<1, 32>>>(16, 32);
    k_gn_coeff<<<1, 256>>>(gn1g, gn1b);

    // 8) conv3 via mma.sync tf32 (reads raw x1, applies GN1+relu on the fly)
    k_conv3_mma<<<dim3(625, 2), 256>>>(x1, wp, gsc, gsh, out);

    // 9) GN2 + relu
    k_gn_reduce<<<16*32, 256>>>(out, 12, 32);
    k_gn_finalize<<<1, 32>>>(12, 32);
    k_gn_norm_relu<<<(192*SP + 255)/256, 256>>>(out, gn2g, gn2b, 192, 12);
}

// round 14
// speedup vs baseline: 1.1508x; 1.1462x over previous
#include <cuda_runtime.h>
#include <math.h>
#include <stdint.h>

// ---------------- problem constants ----------------
#define CAMS   6
#define HEADS  8
#define PTS    2
#define LAYERS 3
#define Dm     256
#define DHh    32
#define FFNd   512
#define NQ     20000
#define IN_C   768
#define FH     8
#define FW     22
#define Lf     176
#define LVIS   44
#define NSP    20000
#define SP     160000
#define X_ELEMS   (192*SP)
#define CAMX_ELEMS (CAMS*IN_C*Lf)

// ---------------- scratch ----------------
__device__ float g_full [CAMS*Lf*IN_C];
__device__ float g_feat [CAMS*Lf*Dm];
__device__ float g_valb [CAMS*Lf*Dm];
__device__ float g_q    [NQ*Dm];
__device__ float g_off  [NQ*HEADS*CAMS*PTS*2];
__device__ float g_att  [NQ*HEADS*CAMS*PTS];
__device__ float g_agg  [NQ*Dm];
__device__ float g_hid  [NQ*FFNd];
__device__ float g_delta[NQ*Dm];
__device__ float g_vol  [Dm*NSP];
__device__ float g_x1   [Dm*SP];
__device__ float g_wp   [27*256*192];
__device__ float g_psum [1024];
__device__ float g_psq  [1024];
__device__ float g_mean [16];
__device__ float g_rstd [16];

__device__ __forceinline__ uint32_t f2tf32(float v) {
    uint32_t o;
    asm("cvt.rna.tf32.f32 %0, %1;" : "=r"(o) : "f"(v));
    return o;
}
#define MMA_TF32(acc, af, b0, b1) \
    asm volatile( \
        "mma.sync.aligned.m16n8k8.row.col.f32.tf32.tf32.f32 " \
        "{%0,%1,%2,%3}, {%4,%5,%6,%7}, {%8,%9}, {%0,%1,%2,%3};" \
        : "+f"((acc)[0]), "+f"((acc)[1]), "+f"((acc)[2]), "+f"((acc)[3]) \
        : "r"((af)[0]), "r"((af)[1]), "r"((af)[2]), "r"((af)[3]), \
          "r"(b0), "r"(b1))

// ---------------- restore full tokens + cam_x ----------------
__global__ void k_build_full(const float* __restrict__ cx, const int* __restrict__ ids,
                             const float* __restrict__ mt, float* __restrict__ full,
                             float* __restrict__ camx, int write_camx)
{
    int i = blockIdx.x * blockDim.x + threadIdx.x;
    if (i >= CAMS*Lf*IN_C) return;
    int c = i % IN_C;
    int l = (i / IN_C) % Lf;
    int n = i / (IN_C*Lf);
    int id = ids[n*Lf + l];
    float v = (id < LVIS) ? cx[((size_t)n*LVIS + id)*IN_C + c] : mt[c];
    full[i] = v;
    if (write_camx)
        camx[((size_t)n*IN_C + c)*Lf + l] = v;
}

// ---------------- generic tiled SGEMM: C = A(MxK) * B(KxN) ----------------
__global__ __launch_bounds__(256)
void k_sgemm_nn(const float* __restrict__ A, const float* __restrict__ B,
                const float* __restrict__ bias, float* __restrict__ C,
                int M, int N, int K, int relu)
{
    __shared__ float As[16][64];
    __shared__ float Bs[16][68];
    int m0 = blockIdx.y * 64, n0 = blockIdx.x * 64;
    int t = threadIdx.x, ty = t >> 4, tx = t & 15;
    float acc[4][4] = {};
    int am = t >> 2, ak = (t & 3) << 2;
    int bk = ty,     bn = tx << 2;

    for (int k0 = 0; k0 < K; k0 += 16) {
        float4 av = make_float4(0.f,0.f,0.f,0.f);
        if (m0 + am < M) av = *(const float4*)(A + (size_t)(m0+am)*K + k0 + ak);
        As[ak+0][am] = av.x; As[ak+1][am] = av.y; As[ak+2][am] = av.z; As[ak+3][am] = av.w;
        float4 bv = make_float4(0.f,0.f,0.f,0.f);
        if (n0 + bn < N) bv = *(const float4*)(B + (size_t)(k0+bk)*N + n0 + bn);
        *(float4*)&Bs[bk][bn] = bv;
        __syncthreads();
        #pragma unroll
        for (int kk = 0; kk < 16; kk++) {
            float4 a = *(const float4*)&As[kk][ty<<2];
            float4 b = *(const float4*)&Bs[kk][tx<<2];
            float av4[4] = {a.x,a.y,a.z,a.w};
            float bv4[4] = {b.x,b.y,b.z,b.w};
            #pragma unroll
            for (int i = 0; i < 4; i++)
                #pragma unroll
                for (int j = 0; j < 4; j++)
                    acc[i][j] += av4[i]*bv4[j];
        }
        __syncthreads();
    }
    #pragma unroll
    for (int i = 0; i < 4; i++) {
        int m = m0 + (ty<<2) + i;
        if (m >= M) continue;
        #pragma unroll
        for (int j = 0; j < 4; j++) {
            int n = n0 + (tx<<2) + j;
            if (n >= N) continue;
            float v = acc[i][j] + (bias ? bias[n] : 0.f);
            if (relu) v = fmaxf(v, 0.f);
            C[(size_t)m*N + n] = v;
        }
    }
}

// ---------------- SGEMM with B transposed ----------------
__global__ __launch_bounds__(256)
void k_sgemm_nt(const float* __restrict__ A, const float* __restrict__ B,
                const float* __restrict__ bias, float* __restrict__ C,
                int M, int N, int K, int relu)
{
    __shared__ float As[16][64];
    __shared__ float Bs[16][68];
    int m0 = blockIdx.y * 64, n0 = blockIdx.x * 64;
    int t = threadIdx.x, ty = t >> 4, tx = t & 15;
    float acc[4][4] = {};
    int lr = t >> 2, lk = (t & 3) << 2;

    for (int k0 = 0; k0 < K; k0 += 16) {
        float4 av = make_float4(0.f,0.f,0.f,0.f);
        if (m0 + lr < M) av = *(const float4*)(A + (size_t)(m0+lr)*K + k0 + lk);
        As[lk+0][lr] = av.x; As[lk+1][lr] = av.y; As[lk+2][lr] = av.z; As[lk+3][lr] = av.w;
        float4 bv = make_float4(0.f,0.f,0.f,0.f);
        if (n0 + lr < N) bv = *(const float4*)(B + (size_t)(n0+lr)*K + k0 + lk);
        Bs[lk+0][lr] = bv.x; Bs[lk+1][lr] = bv.y; Bs[lk+2][lr] = bv.z; Bs[lk+3][lr] = bv.w;
        __syncthreads();
        #pragma unroll
        for (int kk = 0; kk < 16; kk++) {
            float4 a = *(const float4*)&As[kk][ty<<2];
            float4 b = *(const float4*)&Bs[kk][tx<<2];
            float av4[4] = {a.x,a.y,a.z,a.w};
            float bv4[4] = {b.x,b.y,b.z,b.w};
            #pragma unroll
            for (int i = 0; i < 4; i++)
                #pragma unroll
                for (int j = 0; j < 4; j++)
                    acc[i][j] += av4[i]*bv4[j];
        }
        __syncthreads();
    }
    #pragma unroll
    for (int i = 0; i < 4; i++) {
        int m = m0 + (ty<<2) + i;
        if (m >= M) continue;
        #pragma unroll
        for (int j = 0; j < 4; j++) {
            int n = n0 + (tx<<2) + j;
            if (n >= N) continue;
            float v = acc[i][j] + (bias ? bias[n] : 0.f);
            if (relu) v = fmaxf(v, 0.f);
            C[(size_t)m*N + n] = v;
        }
    }
}

// ---------------- tf32 mma GEMM (single-buffered) ----------------
__global__ __launch_bounds__(256)
void k_gemm_tf32(const float* __restrict__ A, const float* __restrict__ B,
                 const float* __restrict__ bias, float* __restrict__ C,
                 int M, int N, int K, int relu)
{
    __shared__ float As[128*17];
    __shared__ float Bs[16][68];
    int t = threadIdx.x;
    int wid = t >> 5, l = t & 31;
    int warp_m = wid & 3, warp_n = wid >> 2;
    int qrow = l >> 2, qcol = l & 3;
    int m0 = blockIdx.y * 128, n0 = blockIdx.x * 64;

    float acc[2][4][4];
    #pragma unroll
    for (int a = 0; a < 2; a++)
        #pragma unroll
        for (int b = 0; b < 4; b++)
            #pragma unroll
            for (int c = 0; c < 4; c++) acc[a][b][c] = 0.f;

    float ldA[8], ldB[4];
    #pragma unroll
    for (int i = 0; i < 8; i++) {
        int e = i*256 + t, m = e >> 4, k = e & 15;
        ldA[i] = (m0 + m < M) ? A[(size_t)(m0+m)*K + k] : 0.f;
    }
    #pragma unroll
    for (int i = 0; i < 4; i++) {
        int e = i*256 + t, k = e >> 6, n = e & 63;
        ldB[i] = (n0 + n < N) ? B[(size_t)k*N + n0 + n] : 0.f;
    }

    int nk = K >> 4;
    for (int c = 0; c < nk; c++) {
        #pragma unroll
        for (int i = 0; i < 8; i++) {
            int e = i*256 + t, m = e >> 4, k = e & 15;
            As[m*17 + k] = __uint_as_float(f2tf32(ldA[i]));
        }
        #pragma unroll
        for (int i = 0; i < 4; i++) {
            int e = i*256 + t, k = e >> 6, n = e & 63;
            Bs[k][n] = __uint_as_float(f2tf32(ldB[i]));
        }
        __syncthreads();
        if (c + 1 < nk) {
            int k0 = (c + 1) << 4;
            #pragma unroll
            for (int i = 0; i < 8; i++) {
                int e = i*256 + t, m = e >> 4, k = e & 15;
                ldA[i] = (m0 + m < M) ? A[(size_t)(m0+m)*K + k0 + k] : 0.f;
            }
            #pragma unroll
            for (int i = 0; i < 4; i++) {
                int e = i*256 + t, k = e >> 6, n = e & 63;
                ldB[i] = (n0 + n < N) ? B[(size_t)(k0+k)*N + n0 + n] : 0.f;
            }
        }
        #pragma unroll
        for (int s8 = 0; s8 < 2; s8++) {
            uint32_t af[2][4];
            #pragma unroll
            for (int mt = 0; mt < 2; mt++) {
                int m = warp_m*32 + mt*16;
                int kb = s8*8 + qcol;
                af[mt][0] = __float_as_uint(As[(m+qrow  )*17 + kb    ]);
                af[mt][1] = __float_as_uint(As[(m+qrow+8)*17 + kb    ]);
                af[mt][2] = __float_as_uint(As[(m+qrow  )*17 + kb + 4]);
                af[mt][3] = __float_as_uint(As[(m+qrow+8)*17 + kb + 4]);
            }
            #pragma unroll
            for (int nt = 0; nt < 4; nt++) {
                int n = warp_n*32 + nt*8 + qrow;
                uint32_t b0 = __float_as_uint(Bs[s8*8 + qcol    ][n]);
                uint32_t b1 = __float_as_uint(Bs[s8*8 + qcol + 4][n]);
                #pragma unroll
                for (int mt = 0; mt < 2; mt++)
                    MMA_TF32(acc[mt][nt], af[mt], b0, b1);
            }
        }
        __syncthreads();
    }

    #pragma unroll
    for (int mt = 0; mt < 2; mt++) {
        int mrow = m0 + warp_m*32 + mt*16 + qrow;
        #pragma unroll
        for (int nt = 0; nt < 4; nt++) {
            int n = n0 + warp_n*32 + nt*8 + qcol*2;
            if (n >= N) continue;
            float b0v = bias ? bias[n]   : 0.f;
            float b1v = bias ? bias[n+1] : 0.f;
            float v0 = acc[mt][nt][0] + b0v, v1 = acc[mt][nt][1] + b1v;
            float v2 = acc[mt][nt][2] + b0v, v3 = acc[mt][nt][3] + b1v;
            if (relu) { v0=fmaxf(v0,0.f); v1=fmaxf(v1,0.f); v2=fmaxf(v2,0.f); v3=fmaxf(v3,0.f); }
            if (mrow < M)     *(float2*)&C[(size_t)mrow*N + n]     = make_float2(v0, v1);
            if (mrow + 8 < M) *(float2*)&C[(size_t)(mrow+8)*N + n] = make_float2(v2, v3);
        }
    }
}

// ---------------- deconv via tf32 mma (single-buffered) ----------------
__global__ __launch_bounds__(256)
void k_deconv_tf32(const float* __restrict__ Wd, const float* __restrict__ V,
                   float* __restrict__ X1)
{
    __shared__ float As[128*17];
    __shared__ float Bs[16][68];
    int t = threadIdx.x;
    int wid = t >> 5, l = t & 31;
    int warp_m = wid & 3, warp_n = wid >> 2;
    int qrow = l >> 2, qcol = l & 3;
    int m0 = blockIdx.y * 128, n0 = blockIdx.x * 64;
    int tap = blockIdx.z;
    int k1 = tap>>2, k2 = (tap>>1)&1, k3 = tap&1;

    float acc[2][4][4];
    #pragma unroll
    for (int a = 0; a < 2; a++)
        #pragma unroll
        for (int b = 0; b < 4; b++)
            #pragma unroll
            for (int c = 0; c < 4; c++) acc[a][b][c] = 0.f;

    float ldA[8], ldB[4];
    #pragma unroll
    for (int i = 0; i < 8; i++) {
        int e = i*256 + t, m = e >> 4, k = e & 15;
        ldA[i] = Wd[(((size_t)(m0+m))*256 + k)*8 + tap];
    }
    #pragma unroll
    for (int i = 0; i < 4; i++) {
        int e = i*256 + t, k = e >> 6, n = e & 63;
        ldB[i] = (n0 + n < NSP) ? V[(size_t)k*NSP + n0 + n] : 0.f;
    }

    for (int c = 0; c < 16; c++) {
        #pragma unroll
        for (int i = 0; i < 8; i++) {
            int e = i*256 + t, m = e >> 4, k = e & 15;
            As[m*17 + k] = __uint_as_float(f2tf32(ldA[i]));
        }
        #pragma unroll
        for (int i = 0; i < 4; i++) {
            int e = i*256 + t, k = e >> 6, n = e & 63;
            Bs[k][n] = __uint_as_float(f2tf32(ldB[i]));
        }
        __syncthreads();
        if (c + 1 < 16) {
            int k0 = (c + 1) << 4;
            #pragma unroll
            for (int i = 0; i < 8; i++) {
                int e = i*256 + t, m = e >> 4, k = e & 15;
                ldA[i] = Wd[(((size_t)(m0+m))*256 + k0 + k)*8 + tap];
            }
            #pragma unroll
            for (int i = 0; i < 4; i++) {
                int e = i*256 + t, k = e >> 6, n = e & 63;
                ldB[i] = (n0 + n < NSP) ? V[(size_t)(k0+k)*NSP + n0 + n] : 0.f;
            }
        }
        #pragma unroll
        for (int s8 = 0; s8 < 2; s8++) {
            uint32_t af[2][4];
            #pragma unroll
            for (int mt = 0; mt < 2; mt++) {
                int m = warp_m*32 + mt*16;
                int kb = s8*8 + qcol;
                af[mt][0] = __float_as_uint(As[(m+qrow  )*17 + kb    ]);
                af[mt][1] = __float_as_uint(As[(m+qrow+8)*17 + kb    ]);
                af[mt][2] = __float_as_uint(As[(m+qrow  )*17 + kb + 4]);
                af[mt][3] = __float_as_uint(As[(m+qrow+8)*17 + kb + 4]);
            }
            #pragma unroll
            for (int nt = 0; nt < 4; nt++) {
                int n = warp_n*32 + nt*8 + qrow;
                uint32_t b0 = __float_as_uint(Bs[s8*8 + qcol    ][n]);
                uint32_t b1 = __float_as_uint(Bs[s8*8 + qcol + 4][n]);
                #pragma unroll
                for (int mt = 0; mt < 2; mt++)
                    MMA_TF32(acc[mt][nt], af[mt], b0, b1);
            }
        }
        __syncthreads();
    }

    #pragma unroll
    for (int mt = 0; mt < 2; mt++) {
        int mrow = m0 + warp_m*32 + mt*16 + qrow;
        #pragma unroll
        for (int nt = 0; nt < 4; nt++) {
            int n = n0 + warp_n*32 + nt*8 + qcol*2;
            #pragma unroll
            for (int j = 0; j < 2; j++) {
                int col = n + j;
                if (col >= NSP) continue;
                int a_ = col/400, b_ = (col>>3)%50, c_ = col&7;
                size_t o = (size_t)(2*a_ + 1 - k1)*1600 + (2*b_ + 1 - k2)*16 + (2*c_ + 1 - k3);
                X1[(size_t)mrow*SP + o]     = acc[mt][nt][j];
                X1[(size_t)(mrow+8)*SP + o] = acc[mt][nt][2+j];
            }
        }
    }
}

// ---------------- feat += embeds ----------------
__global__ void k_add_embeds(float* __restrict__ feat, const float* __restrict__ cams,
                             const float* __restrict__ lvl)
{
    int i = blockIdx.x * blockDim.x + threadIdx.x;
    if (i >= CAMS*Lf*Dm) return;
    int d = i % Dm;
    int n = i / (Lf*Dm);
    feat[i] += cams[n*Dm + d] + lvl[d];
}

// ---------------- deformable sampling with fused softmax ----------------
__global__ void k_sample(const float* __restrict__ val, const float* __restrict__ off,
                         const float* __restrict__ att, float* __restrict__ agg)
{
    int q = blockIdx.x;
    int h = threadIdx.y;
    int lane = threadIdx.x;
    float refx = ((float)(q % 50) + 0.5f) * (22.f/50.f) - 0.5f;
    float refy = ((float)((q/50) % 50) + 0.5f) * (8.f/50.f) - 0.5f;
    const float* offq = off + (size_t)q*192 + h*24;
    const float* attq = att + (size_t)q*96  + h*12;

    float lg = (lane < 12) ? attq[lane] : -1e30f;
    float mx = lg;
    #pragma unroll
    for (int o = 16; o > 0; o >>= 1) mx = fmaxf(mx, __shfl_xor_sync(0xffffffffu, mx, o));
    float e = (lane < 12) ? expf(lg - mx) : 0.f;
    float ssum = e;
    #pragma unroll
    for (int o = 16; o > 0; o >>= 1) ssum += __shfl_xor_sync(0xffffffffu, ssum, o);
    float r = 1.f / ssum;

    float acc = 0.f;
    #pragma unroll
    for (int c = 0; c < CAMS; c++) {
        #pragma unroll
        for (int p = 0; p < PTS; p++) {
            float x = refx + offq[c*4 + p*2 + 0];
            float y = refy + offq[c*4 + p*2 + 1];
            float a = __shfl_sync(0xffffffffu, e, c*2 + p) * r;
            float x0f = floorf(x), y0f = floorf(y);
            float wx = x - x0f, wy = y - y0f;
            int x0 = (int)x0f, y0 = (int)y0f;
            int x0c = min(max(x0,   0), FW-1);
            int x1c = min(max(x0+1, 0), FW-1);
            int y0c = min(max(y0,   0), FH-1);
            int y1c = min(max(y0+1, 0), FH-1);
            const float* vb = val + (size_t)c*Lf*Dm + h*DHh + lane;
            float v00 = vb[(y0c*FW + x0c)*Dm];
            float v01 = vb[(y0c*FW + x1c)*Dm];
            float v10 = vb[(y1c*FW + x0c)*Dm];
            float v11 = vb[(y1c*FW + x1c)*Dm];
            acc += a * ((1.f-wx)*(1.f-wy)*v00 + wx*(1.f-wy)*v01
                      + (1.f-wx)*wy*v10      + wx*wy*v11);
        }
    }
    agg[(size_t)q*Dm + h*DHh + lane] = acc;
}

// ---------------- residual add + LayerNorm(256) ----------------
__global__ void k_ln_residual(float* __restrict__ q, const float* __restrict__ delta,
                              const float* __restrict__ g, const float* __restrict__ b)
{
    int row = blockIdx.x*8 + threadIdx.y;
    int lane = threadIdx.x;
    size_t base = (size_t)row * Dm;
    float v[8]; float s = 0.f;
    #pragma unroll
    for (int i = 0; i < 8; i++) {
        int d = lane + 32*i;
        v[i] = q[base+d] + delta[base+d];
        s += v[i];
    }
    #pragma unroll
    for (int o = 16; o > 0; o >>= 1) s += __shfl_xor_sync(0xffffffffu, s, o);
    float mean = s * (1.f/256.f);
    float s2 = 0.f;
    #pragma unroll
    for (int i = 0; i < 8; i++) { float d0 = v[i]-mean; s2 += d0*d0; }
    #pragma unroll
    for (int o = 16; o > 0; o >>= 1) s2 += __shfl_xor_sync(0xffffffffu, s2, o);
    float rstd = rsqrtf(s2*(1.f/256.f) + 1e-5f);
    #pragma unroll
    for (int i = 0; i < 8; i++) {
        int d = lane + 32*i;
        q[base+d] = (v[i]-mean)*rstd*g[d] + b[d];
    }
}

// ---------------- q -> vol ----------------
__global__ void k_vol(const float* __restrict__ q, float* __restrict__ vol)
{
    int i = blockIdx.x*blockDim.x + threadIdx.x;
    if (i >= Dm*NSP) return;
    int n = i % NSP, ch = i / NSP;
    int a = n/400, b = (n>>3)%50, c = n&7;
    vol[i] = q[((size_t)((c*50 + b)*50 + a))*Dm + ch];
}

// ---------------- GroupNorm: deterministic 2-stage ----------------
__global__ void k_gn_reduce(const float* __restrict__ x, int gc, int nblk)
{
    int g = blockIdx.x / nblk;
    int b = blockIdx.x % nblk;
    size_t E = (size_t)gc * SP;
    size_t chunk = E / nblk;
    const float4* p = (const float4*)(x + (size_t)g*E + (size_t)b*chunk);
    int n4 = (int)(chunk >> 2);
    float s = 0.f, sq = 0.f;
    for (int i = threadIdx.x; i < n4; i += 256) {
        float4 v = p[i];
        s  += v.x + v.y + v.z + v.w;
        sq += v.x*v.x + v.y*v.y + v.z*v.z + v.w*v.w;
    }
    __shared__ float sh[256], sh2[256];
    sh[threadIdx.x] = s; sh2[threadIdx.x] = sq;
    __syncthreads();
    for (int o = 128; o > 0; o >>= 1) {
        if (threadIdx.x < o) { sh[threadIdx.x] += sh[threadIdx.x+o]; sh2[threadIdx.x] += sh2[threadIdx.x+o]; }
        __syncthreads();
    }
    if (threadIdx.x == 0) { g_psum[blockIdx.x] = sh[0]; g_psq[blockIdx.x] = sh2[0]; }
}

__global__ void k_gn_finalize(int gc, int nblk)
{
    int g = threadIdx.x;
    if (g >= 16) return;
    float s = 0.f, sq = 0.f;
    for (int b = 0; b < nblk; b++) { s += g_psum[g*nblk+b]; sq += g_psq[g*nblk+b]; }
    float E = (float)gc * (float)SP;
    float m = s / E;
    float var = sq / E - m*m;
    g_mean[g] = m;
    g_rstd[g] = rsqrtf(var + 1e-5f);
}

__global__ void k_gn_norm_relu(float* __restrict__ x, const float* __restrict__ gamma,
                               const float* __restrict__ beta, int C, int gc)
{
    int i = blockIdx.x*blockDim.x + threadIdx.x;
    if (i >= C*SP) return;
    int ch = i / SP;
    int g = ch / gc;
    float v = (x[i] - g_mean[g]) * g_rstd[g] * gamma[ch] + beta[ch];
    x[i] = fmaxf(v, 0.f);
}

// ---------------- conv3 weight prepack ----------------
__global__ void k_prepack_w(const float* __restrict__ W, float* __restrict__ Wp)
{
    int i = blockIdx.x*blockDim.x + threadIdx.x;
    if (i >= 27*256*192) return;
    int oc = i % 192;
    int ic = (i / 192) % 256;
    int tap = i / (192*256);
    uint32_t v = f2tf32(W[((size_t)oc*256 + ic)*27 + tap]);
    Wp[i] = __uint_as_float(v);
}

// ---------------- conv3 via mma.sync tf32 (single-buffered, R9 form) ----------------
// grid (2, 625): blockIdx.x = oc-block, blockIdx.y = spatial tile.
// Paired CTAs (same y, x=0/1) are launch-adjacent -> co-resident -> share X via L2/L1.
__global__ __launch_bounds__(256, 1)
void k_conv3_mma(const float* __restrict__ X, const float* __restrict__ Wp,
                 float* __restrict__ Out)
{
    __shared__ float As[96*17];
    __shared__ float Bs[16][260];

    int t = threadIdx.x;
    int wid = t >> 5, l = t & 31;
    int warp_m = wid & 1, warp_n = wid >> 1;
    int qrow = l >> 2, qcol = l & 3;
    int n0 = blockIdx.y * 256;
    int ocb = blockIdx.x * 96;

    int s = n0 + t;
    int w = s & 15, h = (s >> 4) % 100, d = s / 1600;

    int ofsA[6], smA[6];
    #pragma unroll
    for (int i = 0; i < 6; i++) {
        int e = i*256 + t;
        int j = e / 96, m = e % 96;
        ofsA[i] = j*192 + ocb + m;
        smA[i]  = m*17 + j;
    }

    float acc[3][8][4];
    #pragma unroll
    for (int a = 0; a < 3; a++)
        #pragma unroll
        for (int b = 0; b < 8; b++)
            #pragma unroll
            for (int c = 0; c < 4; c++) acc[a][b][c] = 0.f;

    float ldB[16], ldA[6];
    int voff = 0; bool vvalid = false;

    {
        int iw = w - 1, ih = h - 1, id = d - 1;
        vvalid = (iw >= 0 && ih >= 0 && id >= 0);
        voff = id*1600 + ih*16 + iw;
        const float* xb = X + (vvalid ? voff : 0);
        #pragma unroll
        for (int j = 0; j < 16; j++)
            ldB[j] = vvalid ? xb[(size_t)j*SP] : 0.f;
        #pragma unroll
        for (int i = 0; i < 6; i++) ldA[i] = Wp[ofsA[i]];
    }

    for (int c = 0; c < 432; c++) {
        #pragma unroll
        for (int j = 0; j < 16; j++)
            Bs[j][t] = __uint_as_float(f2tf32(ldB[j]));
        #pragma unroll
        for (int i = 0; i < 6; i++)
            As[smA[i]] = ldA[i];
        __syncthreads();

        if (c + 1 < 432) {
            int cn = c + 1;
            int tap = cn >> 4, icc = cn & 15;
            if (icc == 0) {
                int kd = tap/9, kh = (tap%9)/3, kw = tap%3;
                int iw = w + kw - 1, ih = h + kh - 1, id = d + kd - 1;
                vvalid = (iw >= 0 && iw < 16 && ih >= 0 && ih < 100 && id >= 0 && id < 100);
                voff = id*1600 + ih*16 + iw;
            }
            const float* xb = X + (size_t)(icc*16)*SP + (vvalid ? voff : 0);
            #pragma unroll
            for (int j = 0; j < 16; j++)
                ldB[j] = vvalid ? xb[(size_t)j*SP] : 0.f;
            const float* wb = Wp + ((size_t)tap*256 + icc*16)*192;
            #pragma unroll
            for (int i = 0; i < 6; i++) ldA[i] = wb[ofsA[i]];
        }

        #pragma unroll
        for (int s8 = 0; s8 < 2; s8++) {
            uint32_t af[3][4];
            #pragma unroll
            for (int mt = 0; mt < 3; mt++) {
                int m = warp_m*48 + mt*16;
                int kb = s8*8 + qcol;
                af[mt][0] = __float_as_uint(As[(m+qrow  )*17 + kb    ]);
                af[mt][1] = __float_as_uint(As[(m+qrow+8)*17 + kb    ]);
                af[mt][2] = __float_as_uint(As[(m+qrow  )*17 + kb + 4]);
                af[mt][3] = __float_as_uint(As[(m+qrow+8)*17 + kb + 4]);
            }
            #pragma unroll
            for (int nt = 0; nt < 8; nt++) {
                int n = warp_n*64 + nt*8 + qrow;
                uint32_t b0 = __float_as_uint(Bs[s8*8 + qcol    ][n]);
                uint32_t b1 = __float_as_uint(Bs[s8*8 + qcol + 4][n]);
                #pragma unroll
                for (int mt = 0; mt < 3; mt++)
                    MMA_TF32(acc[mt][nt], af[mt], b0, b1);
            }
        }
        __syncthreads();
    }

    #pragma unroll
    for (int mt = 0; mt < 3; mt++) {
        int oc0 = ocb + warp_m*48 + mt*16 + qrow;
        #pragma unroll
        for (int nt = 0; nt < 8; nt++) {
            int sp = n0 + warp_n*64 + nt*8 + qcol*2;
            *(float2*)&Out[(size_t)oc0*SP + sp]     = make_float2(acc[mt][nt][0], acc[mt][nt][1]);
            *(float2*)&Out[(size_t)(oc0+8)*SP + sp] = make_float2(acc[mt][nt][2], acc[mt][nt][3]);
        }
    }
}

// ---------------- host launcher ----------------
extern "C" void kernel_launch(void* const* d_in, const int* in_sizes, int n_in,
                              void* d_out, int out_size)
{
    const float* camera_x = (const float*)d_in[0];
    const int*   ids      = (const int*)  d_in[1];
    const float* mask_tok = (const float*)d_in[4];
    const float* vol_emb  = (const float*)d_in[5];
    const float* W_tc     = (const float*)d_in[6];
    const float* b_tc     = (const float*)d_in[7];
    const float* cams_e   = (const float*)d_in[8];
    const float* lvl_e    = (const float*)d_in[9];
    const float* W_off    = (const float*)d_in[10];
    const float* b_off    = (const float*)d_in[11];
    const float* W_att    = (const float*)d_in[12];
    const float* b_att    = (const float*)d_in[13];
    const float* W_val    = (const float*)d_in[14];
    const float* b_val    = (const float*)d_in[15];
    const float* W_out    = (const float*)d_in[16];
    const float* b_out    = (const float*)d_in[17];
    const float* ln1g     = (const float*)d_in[18];
    const float* ln1b     = (const float*)d_in[19];
    const float* W_ff1    = (const float*)d_in[20];
    const float* b_ff1    = (const float*)d_in[21];
    const float* W_ff2    = (const float*)d_in[22];
    const float* b_ff2    = (const float*)d_in[23];
    const float* ln2g     = (const float*)d_in[24];
    const float* ln2b     = (const float*)d_in[25];
    const float* deconv_w = (const float*)d_in[26];
    const float* gn1g     = (const float*)d_in[27];
    const float* gn1b     = (const float*)d_in[28];
    const float* conv3_w  = (const float*)d_in[29];
    const float* gn2g     = (const float*)d_in[30];
    const float* gn2b     = (const float*)d_in[31];
    float* out = (float*)d_out;

    float *full,*feat,*valb,*q,*off,*att,*agg,*hid,*delta,*vol,*x1,*wp;
    cudaGetSymbolAddress((void**)&full,  g_full);
    cudaGetSymbolAddress((void**)&feat,  g_feat);
    cudaGetSymbolAddress((void**)&valb,  g_valb);
    cudaGetSymbolAddress((void**)&q,     g_q);
    cudaGetSymbolAddress((void**)&off,   g_off);
    cudaGetSymbolAddress((void**)&att,   g_att);
    cudaGetSymbolAddress((void**)&agg,   g_agg);
    cudaGetSymbolAddress((void**)&hid,   g_hid);
    cudaGetSymbolAddress((void**)&delta, g_delta);
    cudaGetSymbolAddress((void**)&vol,   g_vol);
    cudaGetSymbolAddress((void**)&x1,    g_x1);
    cudaGetSymbolAddress((void**)&wp,    g_wp);

    int write_camx = (out_size >= X_ELEMS + CAMX_ELEMS) ? 1 : 0;
    float* camx = out + X_ELEMS;

    // 1) restore + cam_x
    k_build_full<<<(CAMS*Lf*IN_C + 255)/256, 256>>>(camera_x, ids, mask_tok, full, camx, write_camx);

    // 1b) prepack conv3 weights
    k_prepack_w<<<(27*256*192 + 255)/256, 256>>>(conv3_w, wp);

    // 2) feat = relu(full @ W_tc^T + b_tc) + embeds
    k_sgemm_nt<<<dim3(4, 17), 256>>>(full, W_tc, b_tc, feat, CAMS*Lf, Dm, IN_C, 1);
    k_add_embeds<<<(CAMS*Lf*Dm + 255)/256, 256>>>(feat, cams_e, lvl_e);

    // 3) q = vol_emb
    cudaMemcpyAsync(q, vol_emb, sizeof(float)*(size_t)NQ*Dm, cudaMemcpyDeviceToDevice, 0);

    // 4) deformable layers
    for (int l = 0; l < LAYERS; l++) {
        k_sgemm_nn<<<dim3(4, 17),  256>>>(feat, W_val + (size_t)l*Dm*Dm,  b_val + l*Dm,  valb, CAMS*Lf, Dm,  Dm, 0);
        k_gemm_tf32<<<dim3(3, 157), 256>>>(q,   W_off + (size_t)l*Dm*192, b_off + l*192, off,  NQ, 192, Dm, 0);
        k_gemm_tf32<<<dim3(2, 157), 256>>>(q,   W_att + (size_t)l*Dm*96,  b_att + l*96,  att,  NQ, 96,  Dm, 0);
        k_sample<<<NQ, dim3(32, 8)>>>(valb, off, att, agg);
        k_gemm_tf32<<<dim3(4, 157), 256>>>(agg, W_out + (size_t)l*Dm*Dm, b_out + l*Dm, delta, NQ, Dm, Dm, 0);
        k_ln_residual<<<NQ/8, dim3(32, 8)>>>(q, delta, ln1g + l*Dm, ln1b + l*Dm);
        k_gemm_tf32<<<dim3(8, 157), 256>>>(q,   W_ff1 + (size_t)l*Dm*FFNd, b_ff1 + l*FFNd, hid,   NQ, FFNd, Dm,   1);
        k_gemm_tf32<<<dim3(4, 157), 256>>>(hid, W_ff2 + (size_t)l*FFNd*Dm, b_ff2 + l*Dm,   delta, NQ, Dm,   FFNd, 0);
        k_ln_residual<<<NQ/8, dim3(32, 8)>>>(q, delta, ln2g + l*Dm, ln2b + l*Dm);
    }

    // 5) vol
    k_vol<<<(Dm*NSP + 255)/256, 256>>>(q, vol);

    // 6) deconv -> x1
    k_deconv_tf32<<<dim3(313, 2, 8), 256>>>(deconv_w, vol, x1);

    // 7) GN1 + relu (separate pass, as in R9)
    k_gn_reduce<<<16*32, 256>>>(x1, 16, 32);
    k_gn_finalize<<<1, 32>>>(16, 32);
    k_gn_norm_relu<<<(Dm*SP + 255)/256, 256>>>(x1, gn1g, gn1b, Dm, 16);

    // 8) conv3 (grid swapped: oc-block fastest -> paired CTAs share X via L2)
    k_conv3_mma<<<dim3(2, 625), 256>>>(x1, wp, out);

    // 9) GN2 + relu
    k_gn_reduce<<<16*32, 256>>>(out, 12, 32);
    k_gn_finalize<<<1, 32>>>(12, 32);
    k_gn_norm_relu<<<(192*SP + 255)/256, 256>>>(out, gn2g, gn2b, 192, 12);
}

// round 16
// speedup vs baseline: 1.4270x; 1.2401x over previous
#include <cuda_runtime.h>
#include <cuda_fp16.h>
#include <math.h>
#include <stdint.h>

// ---------------- problem constants ----------------
#define CAMS   6
#define HEADS  8
#define PTS    2
#define LAYERS 3
#define Dm     256
#define DHh    32
#define FFNd   512
#define NQ     20000
#define IN_C   768
#define FH     8
#define FW     22
#define Lf     176
#define LVIS   44
#define NSP    20000
#define SP     160000
#define X_ELEMS   (192*SP)
#define CAMX_ELEMS (CAMS*IN_C*Lf)

// ---------------- scratch ----------------
__device__ float g_full [CAMS*Lf*IN_C];
__device__ float g_feat [CAMS*Lf*Dm];
__device__ float g_valb [CAMS*Lf*Dm];
__device__ float g_q    [NQ*Dm];
__device__ float g_off  [NQ*HEADS*CAMS*PTS*2];
__device__ float g_att  [NQ*HEADS*CAMS*PTS];
__device__ float g_agg  [NQ*Dm];
__device__ float g_hid  [NQ*FFNd];
__device__ float g_delta[NQ*Dm];
__device__ float g_vol  [Dm*NSP];
__device__ float g_x1   [Dm*SP];
__device__ uint32_t g_wph[27*128*192];    // conv3 weights: half2 pairs [tap][icc][p][oc]
__device__ float g_psum [1024];
__device__ float g_psq  [1024];
__device__ float g_mean [16];
__device__ float g_rstd [16];

__device__ __forceinline__ uint32_t f2tf32(float v) {
    uint32_t o;
    asm("cvt.rna.tf32.f32 %0, %1;" : "=r"(o) : "f"(v));
    return o;
}
#define MMA_TF32(acc, af, b0, b1) \
    asm volatile( \
        "mma.sync.aligned.m16n8k8.row.col.f32.tf32.tf32.f32 " \
        "{%0,%1,%2,%3}, {%4,%5,%6,%7}, {%8,%9}, {%0,%1,%2,%3};" \
        : "+f"((acc)[0]), "+f"((acc)[1]), "+f"((acc)[2]), "+f"((acc)[3]) \
        : "r"((af)[0]), "r"((af)[1]), "r"((af)[2]), "r"((af)[3]), \
          "r"(b0), "r"(b1))
#define MMA_F16(acc, a0, a1, a2, a3, b0, b1) \
    asm volatile( \
        "mma.sync.aligned.m16n8k16.row.col.f32.f16.f16.f32 " \
        "{%0,%1,%2,%3}, {%4,%5,%6,%7}, {%8,%9}, {%0,%1,%2,%3};" \
        : "+f"((acc)[0]), "+f"((acc)[1]), "+f"((acc)[2]), "+f"((acc)[3]) \
        : "r"(a0), "r"(a1), "r"(a2), "r"(a3), "r"(b0), "r"(b1))

// ---------------- restore full tokens + cam_x ----------------
__global__ void k_build_full(const float* __restrict__ cx, const int* __restrict__ ids,
                             const float* __restrict__ mt, float* __restrict__ full,
                             float* __restrict__ camx, int write_camx)
{
    int i = blockIdx.x * blockDim.x + threadIdx.x;
    if (i >= CAMS*Lf*IN_C) return;
    int c = i % IN_C;
    int l = (i / IN_C) % Lf;
    int n = i / (IN_C*Lf);
    int id = ids[n*Lf + l];
    float v = (id < LVIS) ? cx[((size_t)n*LVIS + id)*IN_C + c] : mt[c];
    full[i] = v;
    if (write_camx)
        camx[((size_t)n*IN_C + c)*Lf + l] = v;
}

// ---------------- generic tiled SGEMM: C = A(MxK) * B(KxN) ----------------
__global__ __launch_bounds__(256)
void k_sgemm_nn(const float* __restrict__ A, const float* __restrict__ B,
                const float* __restrict__ bias, float* __restrict__ C,
                int M, int N, int K, int relu)
{
    __shared__ float As[16][64];
    __shared__ float Bs[16][68];
    int m0 = blockIdx.y * 64, n0 = blockIdx.x * 64;
    int t = threadIdx.x, ty = t >> 4, tx = t & 15;
    float acc[4][4] = {};
    int am = t >> 2, ak = (t & 3) << 2;
    int bk = ty,     bn = tx << 2;

    for (int k0 = 0; k0 < K; k0 += 16) {
        float4 av = make_float4(0.f,0.f,0.f,0.f);
        if (m0 + am < M) av = *(const float4*)(A + (size_t)(m0+am)*K + k0 + ak);
        As[ak+0][am] = av.x; As[ak+1][am] = av.y; As[ak+2][am] = av.z; As[ak+3][am] = av.w;
        float4 bv = make_float4(0.f,0.f,0.f,0.f);
        if (n0 + bn < N) bv = *(const float4*)(B + (size_t)(k0+bk)*N + n0 + bn);
        *(float4*)&Bs[bk][bn] = bv;
        __syncthreads();
        #pragma unroll
        for (int kk = 0; kk < 16; kk++) {
            float4 a = *(const float4*)&As[kk][ty<<2];
            float4 b = *(const float4*)&Bs[kk][tx<<2];
            float av4[4] = {a.x,a.y,a.z,a.w};
            float bv4[4] = {b.x,b.y,b.z,b.w};
            #pragma unroll
            for (int i = 0; i < 4; i++)
                #pragma unroll
                for (int j = 0; j < 4; j++)
                    acc[i][j] += av4[i]*bv4[j];
        }
        __syncthreads();
    }
    #pragma unroll
    for (int i = 0; i < 4; i++) {
        int m = m0 + (ty<<2) + i;
        if (m >= M) continue;
        #pragma unroll
        for (int j = 0; j < 4; j++) {
            int n = n0 + (tx<<2) + j;
            if (n >= N) continue;
            float v = acc[i][j] + (bias ? bias[n] : 0.f);
            if (relu) v = fmaxf(v, 0.f);
            C[(size_t)m*N + n] = v;
        }
    }
}

// ---------------- SGEMM with B transposed ----------------
__global__ __launch_bounds__(256)
void k_sgemm_nt(const float* __restrict__ A, const float* __restrict__ B,
                const float* __restrict__ bias, float* __restrict__ C,
                int M, int N, int K, int relu)
{
    __shared__ float As[16][64];
    __shared__ float Bs[16][68];
    int m0 = blockIdx.y * 64, n0 = blockIdx.x * 64;
    int t = threadIdx.x, ty = t >> 4, tx = t & 15;
    float acc[4][4] = {};
    int lr = t >> 2, lk = (t & 3) << 2;

    for (int k0 = 0; k0 < K; k0 += 16) {
        float4 av = make_float4(0.f,0.f,0.f,0.f);
        if (m0 + lr < M) av = *(const float4*)(A + (size_t)(m0+lr)*K + k0 + lk);
        As[lk+0][lr] = av.x; As[lk+1][lr] = av.y; As[lk+2][lr] = av.z; As[lk+3][lr] = av.w;
        float4 bv = make_float4(0.f,0.f,0.f,0.f);
        if (n0 + lr < N) bv = *(const float4*)(B + (size_t)(n0+lr)*K + k0 + lk);
        Bs[lk+0][lr] = bv.x; Bs[lk+1][lr] = bv.y; Bs[lk+2][lr] = bv.z; Bs[lk+3][lr] = bv.w;
        __syncthreads();
        #pragma unroll
        for (int kk = 0; kk < 16; kk++) {
            float4 a = *(const float4*)&As[kk][ty<<2];
            float4 b = *(const float4*)&Bs[kk][tx<<2];
            float av4[4] = {a.x,a.y,a.z,a.w};
            float bv4[4] = {b.x,b.y,b.z,b.w};
            #pragma unroll
            for (int i = 0; i < 4; i++)
                #pragma unroll
                for (int j = 0; j < 4; j++)
                    acc[i][j] += av4[i]*bv4[j];
        }
        __syncthreads();
    }
    #pragma unroll
    for (int i = 0; i < 4; i++) {
        int m = m0 + (ty<<2) + i;
        if (m >= M) continue;
        #pragma unroll
        for (int j = 0; j < 4; j++) {
            int n = n0 + (tx<<2) + j;
            if (n >= N) continue;
            float v = acc[i][j] + (bias ? bias[n] : 0.f);
            if (relu) v = fmaxf(v, 0.f);
            C[(size_t)m*N + n] = v;
        }
    }
}

// ---------------- tf32 mma GEMM (single-buffered) ----------------
__global__ __launch_bounds__(256)
void k_gemm_tf32(const float* __restrict__ A, const float* __restrict__ B,
                 const float* __restrict__ bias, float* __restrict__ C,
                 int M, int N, int K, int relu)
{
    __shared__ float As[128*17];
    __shared__ float Bs[16][68];
    int t = threadIdx.x;
    int wid = t >> 5, l = t & 31;
    int warp_m = wid & 3, warp_n = wid >> 2;
    int qrow = l >> 2, qcol = l & 3;
    int m0 = blockIdx.y * 128, n0 = blockIdx.x * 64;

    float acc[2][4][4];
    #pragma unroll
    for (int a = 0; a < 2; a++)
        #pragma unroll
        for (int b = 0; b < 4; b++)
            #pragma unroll
            for (int c = 0; c < 4; c++) acc[a][b][c] = 0.f;

    float ldA[8], ldB[4];
    #pragma unroll
    for (int i = 0; i < 8; i++) {
        int e = i*256 + t, m = e >> 4, k = e & 15;
        ldA[i] = (m0 + m < M) ? A[(size_t)(m0+m)*K + k] : 0.f;
    }
    #pragma unroll
    for (int i = 0; i < 4; i++) {
        int e = i*256 + t, k = e >> 6, n = e & 63;
        ldB[i] = (n0 + n < N) ? B[(size_t)k*N + n0 + n] : 0.f;
    }

    int nk = K >> 4;
    for (int c = 0; c < nk; c++) {
        #pragma unroll
        for (int i = 0; i < 8; i++) {
            int e = i*256 + t, m = e >> 4, k = e & 15;
            As[m*17 + k] = __uint_as_float(f2tf32(ldA[i]));
        }
        #pragma unroll
        for (int i = 0; i < 4; i++) {
            int e = i*256 + t, k = e >> 6, n = e & 63;
            Bs[k][n] = __uint_as_float(f2tf32(ldB[i]));
        }
        __syncthreads();
        if (c + 1 < nk) {
            int k0 = (c + 1) << 4;
            #pragma unroll
            for (int i = 0; i < 8; i++) {
                int e = i*256 + t, m = e >> 4, k = e & 15;
                ldA[i] = (m0 + m < M) ? A[(size_t)(m0+m)*K + k0 + k] : 0.f;
            }
            #pragma unroll
            for (int i = 0; i < 4; i++) {
                int e = i*256 + t, k = e >> 6, n = e & 63;
                ldB[i] = (n0 + n < N) ? B[(size_t)(k0+k)*N + n0 + n] : 0.f;
            }
        }
        #pragma unroll
        for (int s8 = 0; s8 < 2; s8++) {
            uint32_t af[2][4];
            #pragma unroll
            for (int mt = 0; mt < 2; mt++) {
                int m = warp_m*32 + mt*16;
                int kb = s8*8 + qcol;
                af[mt][0] = __float_as_uint(As[(m+qrow  )*17 + kb    ]);
                af[mt][1] = __float_as_uint(As[(m+qrow+8)*17 + kb    ]);
                af[mt][2] = __float_as_uint(As[(m+qrow  )*17 + kb + 4]);
                af[mt][3] = __float_as_uint(As[(m+qrow+8)*17 + kb + 4]);
            }
            #pragma unroll
            for (int nt = 0; nt < 4; nt++) {
                int n = warp_n*32 + nt*8 + qrow;
                uint32_t b0 = __float_as_uint(Bs[s8*8 + qcol    ][n]);
                uint32_t b1 = __float_as_uint(Bs[s8*8 + qcol + 4][n]);
                #pragma unroll
                for (int mt = 0; mt < 2; mt++)
                    MMA_TF32(acc[mt][nt], af[mt], b0, b1);
            }
        }
        __syncthreads();
    }

    #pragma unroll
    for (int mt = 0; mt < 2; mt++) {
        int mrow = m0 + warp_m*32 + mt*16 + qrow;
        #pragma unroll
        for (int nt = 0; nt < 4; nt++) {
            int n = n0 + warp_n*32 + nt*8 + qcol*2;
            if (n >= N) continue;
            float b0v = bias ? bias[n]   : 0.f;
            float b1v = bias ? bias[n+1] : 0.f;
            float v0 = acc[mt][nt][0] + b0v, v1 = acc[mt][nt][1] + b1v;
            float v2 = acc[mt][nt][2] + b0v, v3 = acc[mt][nt][3] + b1v;
            if (relu) { v0=fmaxf(v0,0.f); v1=fmaxf(v1,0.f); v2=fmaxf(v2,0.f); v3=fmaxf(v3,0.f); }
            if (mrow < M)     *(float2*)&C[(size_t)mrow*N + n]     = make_float2(v0, v1);
            if (mrow + 8 < M) *(float2*)&C[(size_t)(mrow+8)*N + n] = make_float2(v2, v3);
        }
    }
}

// ---------------- deconv via tf32 mma (single-buffered) ----------------
__global__ __launch_bounds__(256)
void k_deconv_tf32(const float* __restrict__ Wd, const float* __restrict__ V,
                   float* __restrict__ X1)
{
    __shared__ float As[128*17];
    __shared__ float Bs[16][68];
    int t = threadIdx.x;
    int wid = t >> 5, l = t & 31;
    int warp_m = wid & 3, warp_n = wid >> 2;
    int qrow = l >> 2, qcol = l & 3;
    int m0 = blockIdx.y * 128, n0 = blockIdx.x * 64;
    int tap = blockIdx.z;
    int k1 = tap>>2, k2 = (tap>>1)&1, k3 = tap&1;

    float acc[2][4][4];
    #pragma unroll
    for (int a = 0; a < 2; a++)
        #pragma unroll
        for (int b = 0; b < 4; b++)
            #pragma unroll
            for (int c = 0; c < 4; c++) acc[a][b][c] = 0.f;

    float ldA[8], ldB[4];
    #pragma unroll
    for (int i = 0; i < 8; i++) {
        int e = i*256 + t, m = e >> 4, k = e & 15;
        ldA[i] = Wd[(((size_t)(m0+m))*256 + k)*8 + tap];
    }
    #pragma unroll
    for (int i = 0; i < 4; i++) {
        int e = i*256 + t, k = e >> 6, n = e & 63;
        ldB[i] = (n0 + n < NSP) ? V[(size_t)k*NSP + n0 + n] : 0.f;
    }

    for (int c = 0; c < 16; c++) {
        #pragma unroll
        for (int i = 0; i < 8; i++) {
            int e = i*256 + t, m = e >> 4, k = e & 15;
            As[m*17 + k] = __uint_as_float(f2tf32(ldA[i]));
        }
        #pragma unroll
        for (int i = 0; i < 4; i++) {
            int e = i*256 + t, k = e >> 6, n = e & 63;
            Bs[k][n] = __uint_as_float(f2tf32(ldB[i]));
        }
        __syncthreads();
        if (c + 1 < 16) {
            int k0 = (c + 1) << 4;
            #pragma unroll
            for (int i = 0; i < 8; i++) {
                int e = i*256 + t, m = e >> 4, k = e & 15;
                ldA[i] = Wd[(((size_t)(m0+m))*256 + k0 + k)*8 + tap];
            }
            #pragma unroll
            for (int i = 0; i < 4; i++) {
                int e = i*256 + t, k = e >> 6, n = e & 63;
                ldB[i] = (n0 + n < NSP) ? V[(size_t)(k0+k)*NSP + n0 + n] : 0.f;
            }
        }
        #pragma unroll
        for (int s8 = 0; s8 < 2; s8++) {
            uint32_t af[2][4];
            #pragma unroll
            for (int mt = 0; mt < 2; mt++) {
                int m = warp_m*32 + mt*16;
                int kb = s8*8 + qcol;
                af[mt][0] = __float_as_uint(As[(m+qrow  )*17 + kb    ]);
                af[mt][1] = __float_as_uint(As[(m+qrow+8)*17 + kb    ]);
                af[mt][2] = __float_as_uint(As[(m+qrow  )*17 + kb + 4]);
                af[mt][3] = __float_as_uint(As[(m+qrow+8)*17 + kb + 4]);
            }
            #pragma unroll
            for (int nt = 0; nt < 4; nt++) {
                int n = warp_n*32 + nt*8 + qrow;
                uint32_t b0 = __float_as_uint(Bs[s8*8 + qcol    ][n]);
                uint32_t b1 = __float_as_uint(Bs[s8*8 + qcol + 4][n]);
                #pragma unroll
                for (int mt = 0; mt < 2; mt++)
                    MMA_TF32(acc[mt][nt], af[mt], b0, b1);
            }
        }
        __syncthreads();
    }

    #pragma unroll
    for (int mt = 0; mt < 2; mt++) {
        int mrow = m0 + warp_m*32 + mt*16 + qrow;
        #pragma unroll
        for (int nt = 0; nt < 4; nt++) {
            int n = n0 + warp_n*32 + nt*8 + qcol*2;
            #pragma unroll
            for (int j = 0; j < 2; j++) {
                int col = n + j;
                if (col >= NSP) continue;
                int a_ = col/400, b_ = (col>>3)%50, c_ = col&7;
                size_t o = (size_t)(2*a_ + 1 - k1)*1600 + (2*b_ + 1 - k2)*16 + (2*c_ + 1 - k3);
                X1[(size_t)mrow*SP + o]     = acc[mt][nt][j];
                X1[(size_t)(mrow+8)*SP + o] = acc[mt][nt][2+j];
            }
        }
    }
}

// ---------------- feat += embeds ----------------
__global__ void k_add_embeds(float* __restrict__ feat, const float* __restrict__ cams,
                             const float* __restrict__ lvl)
{
    int i = blockIdx.x * blockDim.x + threadIdx.x;
    if (i >= CAMS*Lf*Dm) return;
    int d = i % Dm;
    int n = i / (Lf*Dm);
    feat[i] += cams[n*Dm + d] + lvl[d];
}

// ---------------- deformable sampling with fused softmax ----------------
__global__ void k_sample(const float* __restrict__ val, const float* __restrict__ off,
                         const float* __restrict__ att, float* __restrict__ agg)
{
    int q = blockIdx.x;
    int h = threadIdx.y;
    int lane = threadIdx.x;
    float refx = ((float)(q % 50) + 0.5f) * (22.f/50.f) - 0.5f;
    float refy = ((float)((q/50) % 50) + 0.5f) * (8.f/50.f) - 0.5f;
    const float* offq = off + (size_t)q*192 + h*24;
    const float* attq = att + (size_t)q*96  + h*12;

    float lg = (lane < 12) ? attq[lane] : -1e30f;
    float mx = lg;
    #pragma unroll
    for (int o = 16; o > 0; o >>= 1) mx = fmaxf(mx, __shfl_xor_sync(0xffffffffu, mx, o));
    float e = (lane < 12) ? expf(lg - mx) : 0.f;
    float ssum = e;
    #pragma unroll
    for (int o = 16; o > 0; o >>= 1) ssum += __shfl_xor_sync(0xffffffffu, ssum, o);
    float r = 1.f / ssum;

    float acc = 0.f;
    #pragma unroll
    for (int c = 0; c < CAMS; c++) {
        #pragma unroll
        for (int p = 0; p < PTS; p++) {
            float x = refx + offq[c*4 + p*2 + 0];
            float y = refy + offq[c*4 + p*2 + 1];
            float a = __shfl_sync(0xffffffffu, e, c*2 + p) * r;
            float x0f = floorf(x), y0f = floorf(y);
            float wx = x - x0f, wy = y - y0f;
            int x0 = (int)x0f, y0 = (int)y0f;
            int x0c = min(max(x0,   0), FW-1);
            int x1c = min(max(x0+1, 0), FW-1);
            int y0c = min(max(y0,   0), FH-1);
            int y1c = min(max(y0+1, 0), FH-1);
            const float* vb = val + (size_t)c*Lf*Dm + h*DHh + lane;
            float v00 = vb[(y0c*FW + x0c)*Dm];
            float v01 = vb[(y0c*FW + x1c)*Dm];
            float v10 = vb[(y1c*FW + x0c)*Dm];
            float v11 = vb[(y1c*FW + x1c)*Dm];
            acc += a * ((1.f-wx)*(1.f-wy)*v00 + wx*(1.f-wy)*v01
                      + (1.f-wx)*wy*v10      + wx*wy*v11);
        }
    }
    agg[(size_t)q*Dm + h*DHh + lane] = acc;
}

// ---------------- residual add + LayerNorm(256) ----------------
__global__ void k_ln_residual(float* __restrict__ q, const float* __restrict__ delta,
                              const float* __restrict__ g, const float* __restrict__ b)
{
    int row = blockIdx.x*8 + threadIdx.y;
    int lane = threadIdx.x;
    size_t base = (size_t)row * Dm;
    float v[8]; float s = 0.f;
    #pragma unroll
    for (int i = 0; i < 8; i++) {
        int d = lane + 32*i;
        v[i] = q[base+d] + delta[base+d];
        s += v[i];
    }
    #pragma unroll
    for (int o = 16; o > 0; o >>= 1) s += __shfl_xor_sync(0xffffffffu, s, o);
    float mean = s * (1.f/256.f);
    float s2 = 0.f;
    #pragma unroll
    for (int i = 0; i < 8; i++) { float d0 = v[i]-mean; s2 += d0*d0; }
    #pragma unroll
    for (int o = 16; o > 0; o >>= 1) s2 += __shfl_xor_sync(0xffffffffu, s2, o);
    float rstd = rsqrtf(s2*(1.f/256.f) + 1e-5f);
    #pragma unroll
    for (int i = 0; i < 8; i++) {
        int d = lane + 32*i;
        q[base+d] = (v[i]-mean)*rstd*g[d] + b[d];
    }
}

// ---------------- q -> vol ----------------
__global__ void k_vol(const float* __restrict__ q, float* __restrict__ vol)
{
    int i = blockIdx.x*blockDim.x + threadIdx.x;
    if (i >= Dm*NSP) return;
    int n = i % NSP, ch = i / NSP;
    int a = n/400, b = (n>>3)%50, c = n&7;
    vol[i] = q[((size_t)((c*50 + b)*50 + a))*Dm + ch];
}

// ---------------- GroupNorm: deterministic 2-stage ----------------
__global__ void k_gn_reduce(const float* __restrict__ x, int gc, int nblk)
{
    int g = blockIdx.x / nblk;
    int b = blockIdx.x % nblk;
    size_t E = (size_t)gc * SP;
    size_t chunk = E / nblk;
    const float4* p = (const float4*)(x + (size_t)g*E + (size_t)b*chunk);
    int n4 = (int)(chunk >> 2);
    float s = 0.f, sq = 0.f;
    for (int i = threadIdx.x; i < n4; i += 256) {
        float4 v = p[i];
        s  += v.x + v.y + v.z + v.w;
        sq += v.x*v.x + v.y*v.y + v.z*v.z + v.w*v.w;
    }
    __shared__ float sh[256], sh2[256];
    sh[threadIdx.x] = s; sh2[threadIdx.x] = sq;
    __syncthreads();
    for (int o = 128; o > 0; o >>= 1) {
        if (threadIdx.x < o) { sh[threadIdx.x] += sh[threadIdx.x+o]; sh2[threadIdx.x] += sh2[threadIdx.x+o]; }
        __syncthreads();
    }
    if (threadIdx.x == 0) { g_psum[blockIdx.x] = sh[0]; g_psq[blockIdx.x] = sh2[0]; }
}

__global__ void k_gn_finalize(int gc, int nblk)
{
    int g = threadIdx.x;
    if (g >= 16) return;
    float s = 0.f, sq = 0.f;
    for (int b = 0; b < nblk; b++) { s += g_psum[g*nblk+b]; sq += g_psq[g*nblk+b]; }
    float E = (float)gc * (float)SP;
    float m = s / E;
    float var = sq / E - m*m;
    g_mean[g] = m;
    g_rstd[g] = rsqrtf(var + 1e-5f);
}

__global__ void k_gn_norm_relu(float* __restrict__ x, const float* __restrict__ gamma,
                               const float* __restrict__ beta, int C, int gc)
{
    int i = blockIdx.x*blockDim.x + threadIdx.x;
    if (i >= C*SP) return;
    int ch = i / SP;
    int g = ch / gc;
    float v = (x[i] - g_mean[g]) * g_rstd[g] * gamma[ch] + beta[ch];
    x[i] = fmaxf(v, 0.f);
}

// ---------------- conv3 weight prepack: half2 k-pairs [tap][icc][p][oc] ----------------
// tap in [0,27), icc in [0,16), p in [0,8), oc in [0,192): ic = icc*16 + 2p (+0/1)
__global__ void k_prepack_wh(const float* __restrict__ W, uint32_t* __restrict__ Wp)
{
    int i = blockIdx.x*blockDim.x + threadIdx.x;
    if (i >= 27*128*192) return;
    int oc  = i % 192;
    int p   = (i / 192) & 7;
    int icc = (i / 1536) & 15;
    int tap = i / 24576;
    int ic  = icc*16 + 2*p;
    float w0 = W[((size_t)oc*256 + ic  )*27 + tap];
    float w1 = W[((size_t)oc*256 + ic+1)*27 + tap];
    __half2 h = __floats2half2_rn(w0, w1);
    Wp[i] = *(uint32_t*)&h;
}

// ---------------- conv3 via mma.sync fp16 m16n8k16 ----------------
// grid (2, 625). CTA: 96 oc x 256 sp, K = 27*256 in 432 chunks of 16.
__global__ __launch_bounds__(256)
void k_conv3_mma(const float* __restrict__ X, const uint32_t* __restrict__ Wph,
                 float* __restrict__ Out)
{
    __shared__ uint32_t As2[96*12];      // [m][kpair], stride 12
    __shared__ uint32_t Bs2[8][260];     // [kpair][sp]

    int t = threadIdx.x;
    int wid = t >> 5, l = t & 31;
    int warp_m = wid & 1, warp_n = wid >> 1;
    int qrow = l >> 2, qcol = l & 3;
    int n0 = blockIdx.y * 256;
    int ocb = blockIdx.x * 96;

    int s = n0 + t;
    int w = s & 15, h = (s >> 4) % 100, d = s / 1600;

    int ofsA[3], smA[3];
    #pragma unroll
    for (int i = 0; i < 3; i++) {
        int e = i*256 + t;
        int m = e % 96, p = e / 96;
        ofsA[i] = p*192 + ocb + m;
        smA[i]  = m*12 + p;
    }

    float acc[3][8][4];
    #pragma unroll
    for (int a = 0; a < 3; a++)
        #pragma unroll
        for (int b = 0; b < 8; b++)
            #pragma unroll
            for (int c = 0; c < 4; c++) acc[a][b][c] = 0.f;

    float ldB[16];
    uint32_t ldA[3];
    int voff = 0; bool vvalid = false;

    {
        int iw = w - 1, ih = h - 1, id = d - 1;
        vvalid = (iw >= 0 && ih >= 0 && id >= 0);
        voff = id*1600 + ih*16 + iw;
        const float* xb = X + (vvalid ? voff : 0);
        #pragma unroll
        for (int j = 0; j < 16; j++)
            ldB[j] = vvalid ? xb[(size_t)j*SP] : 0.f;
        #pragma unroll
        for (int i = 0; i < 3; i++) ldA[i] = Wph[ofsA[i]];
    }

    for (int c = 0; c < 432; c++) {
        #pragma unroll
        for (int p = 0; p < 8; p++) {
            __half2 hv = __floats2half2_rn(ldB[2*p], ldB[2*p+1]);
            Bs2[p][t] = *(uint32_t*)&hv;
        }
        #pragma unroll
        for (int i = 0; i < 3; i++)
            As2[smA[i]] = ldA[i];
        __syncthreads();

        if (c + 1 < 432) {
            int cn = c + 1;
            int tap = cn >> 4, icc = cn & 15;
            if (icc == 0) {
                int kd = tap/9, kh = (tap%9)/3, kw = tap%3;
                int iw = w + kw - 1, ih = h + kh - 1, id = d + kd - 1;
                vvalid = (iw >= 0 && iw < 16 && ih >= 0 && ih < 100 && id >= 0 && id < 100);
                voff = id*1600 + ih*16 + iw;
            }
            const float* xb = X + (size_t)(icc*16)*SP + (vvalid ? voff : 0);
            #pragma unroll
            for (int j = 0; j < 16; j++)
                ldB[j] = vvalid ? xb[(size_t)j*SP] : 0.f;
            const uint32_t* wb = Wph + (size_t)(tap*16 + icc)*1536;
            #pragma unroll
            for (int i = 0; i < 3; i++) ldA[i] = wb[ofsA[i]];
        }

        #pragma unroll
        for (int mt = 0; mt < 3; mt++) {
            int m = warp_m*48 + mt*16;
            uint32_t a0 = As2[(m+qrow  )*12 + qcol    ];
            uint32_t a1 = As2[(m+qrow+8)*12 + qcol    ];
            uint32_t a2 = As2[(m+qrow  )*12 + qcol + 4];
            uint32_t a3 = As2[(m+qrow+8)*12 + qcol + 4];
            #pragma unroll
            for (int nt = 0; nt < 8; nt++) {
                int n = warp_n*64 + nt*8 + qrow;
                uint32_t b0 = Bs2[qcol    ][n];
                uint32_t b1 = Bs2[qcol + 4][n];
                MMA_F16(acc[mt][nt], a0, a1, a2, a3, b0, b1);
            }
        }
        __syncthreads();
    }

    #pragma unroll
    for (int mt = 0; mt < 3; mt++) {
        int oc0 = ocb + warp_m*48 + mt*16 + qrow;
        #pragma unroll
        for (int nt = 0; nt < 8; nt++) {
            int sp = n0 + warp_n*64 + nt*8 + qcol*2;
            *(float2*)&Out[(size_t)oc0*SP + sp]     = make_float2(acc[mt][nt][0], acc[mt][nt][1]);
            *(float2*)&Out[(size_t)(oc0+8)*SP + sp] = make_float2(acc[mt][nt][2], acc[mt][nt][3]);
        }
    }
}

// ---------------- host launcher ----------------
extern "C" void kernel_launch(void* const* d_in, const int* in_sizes, int n_in,
                              void* d_out, int out_size)
{
    const float* camera_x = (const float*)d_in[0];
    const int*   ids      = (const int*)  d_in[1];
    const float* mask_tok = (const float*)d_in[4];
    const float* vol_emb  = (const float*)d_in[5];
    const float* W_tc     = (const float*)d_in[6];
    const float* b_tc     = (const float*)d_in[7];
    const float* cams_e   = (const float*)d_in[8];
    const float* lvl_e    = (const float*)d_in[9];
    const float* W_off    = (const float*)d_in[10];
    const float* b_off    = (const float*)d_in[11];
    const float* W_att    = (const float*)d_in[12];
    const float* b_att    = (const float*)d_in[13];
    const float* W_val    = (const float*)d_in[14];
    const float* b_val    = (const float*)d_in[15];
    const float* W_out    = (const float*)d_in[16];
    const float* b_out    = (const float*)d_in[17];
    const float* ln1g     = (const float*)d_in[18];
    const float* ln1b     = (const float*)d_in[19];
    const float* W_ff1    = (const float*)d_in[20];
    const float* b_ff1    = (const float*)d_in[21];
    const float* W_ff2    = (const float*)d_in[22];
    const float* b_ff2    = (const float*)d_in[23];
    const float* ln2g     = (const float*)d_in[24];
    const float* ln2b     = (const float*)d_in[25];
    const float* deconv_w = (const float*)d_in[26];
    const float* gn1g     = (const float*)d_in[27];
    const float* gn1b     = (const float*)d_in[28];
    const float* conv3_w  = (const float*)d_in[29];
    const float* gn2g     = (const float*)d_in[30];
    const float* gn2b     = (const float*)d_in[31];
    float* out = (float*)d_out;

    float *full,*feat,*valb,*q,*off,*att,*agg,*hid,*delta,*vol,*x1;
    uint32_t *wph;
    cudaGetSymbolAddress((void**)&full,  g_full);
    cudaGetSymbolAddress((void**)&feat,  g_feat);
    cudaGetSymbolAddress((void**)&valb,  g_valb);
    cudaGetSymbolAddress((void**)&q,     g_q);
    cudaGetSymbolAddress((void**)&off,   g_off);
    cudaGetSymbolAddress((void**)&att,   g_att);
    cudaGetSymbolAddress((void**)&agg,   g_agg);
    cudaGetSymbolAddress((void**)&hid,   g_hid);
    cudaGetSymbolAddress((void**)&delta, g_delta);
    cudaGetSymbolAddress((void**)&vol,   g_vol);
    cudaGetSymbolAddress((void**)&x1,    g_x1);
    cudaGetSymbolAddress((void**)&wph,   g_wph);

    int write_camx = (out_size >= X_ELEMS + CAMX_ELEMS) ? 1 : 0;
    float* camx = out + X_ELEMS;

    // 1) restore + cam_x
    k_build_full<<<(CAMS*Lf*IN_C + 255)/256, 256>>>(camera_x, ids, mask_tok, full, camx, write_camx);

    // 1b) prepack conv3 weights (fp16 half2 pairs, full 256 ic per tap)
    k_prepack_wh<<<(27*128*192 + 255)/256, 256>>>(conv3_w, wph);

    // 2) feat = relu(full @ W_tc^T + b_tc) + embeds
    k_sgemm_nt<<<dim3(4, 17), 256>>>(full, W_tc, b_tc, feat, CAMS*Lf, Dm, IN_C, 1);
    k_add_embeds<<<(CAMS*Lf*Dm + 255)/256, 256>>>(feat, cams_e, lvl_e);

    // 3) q = vol_emb
    cudaMemcpyAsync(q, vol_emb, sizeof(float)*(size_t)NQ*Dm, cudaMemcpyDeviceToDevice, 0);

    // 4) deformable layers
    for (int l = 0; l < LAYERS; l++) {
        k_sgemm_nn<<<dim3(4, 17),  256>>>(feat, W_val + (size_t)l*Dm*Dm,  b_val + l*Dm,  valb, CAMS*Lf, Dm,  Dm, 0);
        k_gemm_tf32<<<dim3(3, 157), 256>>>(q,   W_off + (size_t)l*Dm*192, b_off + l*192, off,  NQ, 192, Dm, 0);
        k_gemm_tf32<<<dim3(2, 157), 256>>>(q,   W_att + (size_t)l*Dm*96,  b_att + l*96,  att,  NQ, 96,  Dm, 0);
        k_sample<<<NQ, dim3(32, 8)>>>(valb, off, att, agg);
        k_gemm_tf32<<<dim3(4, 157), 256>>>(agg, W_out + (size_t)l*Dm*Dm, b_out + l*Dm, delta, NQ, Dm, Dm, 0);
        k_ln_residual<<<NQ/8, dim3(32, 8)>>>(q, delta, ln1g + l*Dm, ln1b + l*Dm);
        k_gemm_tf32<<<dim3(8, 157), 256>>>(q,   W_ff1 + (size_t)l*Dm*FFNd, b_ff1 + l*FFNd, hid,   NQ, FFNd, Dm,   1);
        k_gemm_tf32<<<dim3(4, 157), 256>>>(hid, W_ff2 + (size_t)l*FFNd*Dm, b_ff2 + l*Dm,   delta, NQ, Dm,   FFNd, 0);
        k_ln_residual<<<NQ/8, dim3(32, 8)>>>(q, delta, ln2g + l*Dm, ln2b + l*Dm);
    }

    // 5) vol
    k_vol<<<(Dm*NSP + 255)/256, 256>>>(q, vol);

    // 6) deconv -> x1
    k_deconv_tf32<<<dim3(313, 2, 8), 256>>>(deconv_w, vol, x1);

    // 7) GN1 + relu
    k_gn_reduce<<<16*32, 256>>>(x1, 16, 32);
    k_gn_finalize<<<1, 32>>>(16, 32);
    k_gn_norm_relu<<<(Dm*SP + 255)/256, 256>>>(x1, gn1g, gn1b, Dm, 16);

    // 8) conv3 via mma.sync fp16
    k_conv3_mma<<<dim3(2, 625), 256>>>(x1, wph, out);

    // 9) GN2 + relu
    k_gn_reduce<<<16*32, 256>>>(out, 12, 32);
    k_gn_finalize<<<1, 32>>>(12, 32);
    k_gn_norm_relu<<<(192*SP + 255)/256, 256>>>(out, gn2g, gn2b, 192, 12);
}

// round 17
// speedup vs baseline: 1.5575x; 1.0915x over previous
#include <cuda_runtime.h>
#include <cuda_fp16.h>
#include <math.h>
#include <stdint.h>

// ---------------- problem constants ----------------
#define CAMS   6
#define HEADS  8
#define PTS    2
#define LAYERS 3
#define Dm     256
#define DHh    32
#define FFNd   512
#define NQ     20000
#define IN_C   768
#define FH     8
#define FW     22
#define Lf     176
#define LVIS   44
#define NSP    20000
#define SP     160000
#define X_ELEMS   (192*SP)
#define CAMX_ELEMS (CAMS*IN_C*Lf)

// ---------------- scratch ----------------
__device__ float g_full [CAMS*Lf*IN_C];
__device__ float g_feat [CAMS*Lf*Dm];
__device__ float g_valb [CAMS*Lf*Dm];
__device__ float g_q    [NQ*Dm];
__device__ float g_off  [NQ*HEADS*CAMS*PTS*2];
__device__ float g_att  [NQ*HEADS*CAMS*PTS];
__device__ float g_agg  [NQ*Dm];
__device__ float g_hid  [NQ*FFNd];
__device__ float g_delta[NQ*Dm];
__device__ float g_vol  [Dm*NSP];
__device__ float g_x1   [Dm*SP];
__device__ uint32_t g_wph[27*128*192];    // conv3 weights: half2 pairs [tap][icc][p][oc]
__device__ float g_psum [1024];
__device__ float g_psq  [1024];
__device__ float g_mean [16];
__device__ float g_rstd [16];

#define MMA_F16(acc, a0, a1, a2, a3, b0, b1) \
    asm volatile( \
        "mma.sync.aligned.m16n8k16.row.col.f32.f16.f16.f32 " \
        "{%0,%1,%2,%3}, {%4,%5,%6,%7}, {%8,%9}, {%0,%1,%2,%3};" \
        : "+f"((acc)[0]), "+f"((acc)[1]), "+f"((acc)[2]), "+f"((acc)[3]) \
        : "r"(a0), "r"(a1), "r"(a2), "r"(a3), "r"(b0), "r"(b1))

__device__ __forceinline__ uint32_t h2pack(float a, float b) {
    __half2 h = __floats2half2_rn(a, b);
    return *(uint32_t*)&h;
}

// ---------------- restore full tokens + cam_x ----------------
__global__ void k_build_full(const float* __restrict__ cx, const int* __restrict__ ids,
                             const float* __restrict__ mt, float* __restrict__ full,
                             float* __restrict__ camx, int write_camx)
{
    int i = blockIdx.x * blockDim.x + threadIdx.x;
    if (i >= CAMS*Lf*IN_C) return;
    int c = i % IN_C;
    int l = (i / IN_C) % Lf;
    int n = i / (IN_C*Lf);
    int id = ids[n*Lf + l];
    float v = (id < LVIS) ? cx[((size_t)n*LVIS + id)*IN_C + c] : mt[c];
    full[i] = v;
    if (write_camx)
        camx[((size_t)n*IN_C + c)*Lf + l] = v;
}

// ---------------- generic tiled SGEMM: C = A(MxK) * B(KxN) ----------------
__global__ __launch_bounds__(256)
void k_sgemm_nn(const float* __restrict__ A, const float* __restrict__ B,
                const float* __restrict__ bias, float* __restrict__ C,
                int M, int N, int K, int relu)
{
    __shared__ float As[16][64];
    __shared__ float Bs[16][68];
    int m0 = blockIdx.y * 64, n0 = blockIdx.x * 64;
    int t = threadIdx.x, ty = t >> 4, tx = t & 15;
    float acc[4][4] = {};
    int am = t >> 2, ak = (t & 3) << 2;
    int bk = ty,     bn = tx << 2;

    for (int k0 = 0; k0 < K; k0 += 16) {
        float4 av = make_float4(0.f,0.f,0.f,0.f);
        if (m0 + am < M) av = *(const float4*)(A + (size_t)(m0+am)*K + k0 + ak);
        As[ak+0][am] = av.x; As[ak+1][am] = av.y; As[ak+2][am] = av.z; As[ak+3][am] = av.w;
        float4 bv = make_float4(0.f,0.f,0.f,0.f);
        if (n0 + bn < N) bv = *(const float4*)(B + (size_t)(k0+bk)*N + n0 + bn);
        *(float4*)&Bs[bk][bn] = bv;
        __syncthreads();
        #pragma unroll
        for (int kk = 0; kk < 16; kk++) {
            float4 a = *(const float4*)&As[kk][ty<<2];
            float4 b = *(const float4*)&Bs[kk][tx<<2];
            float av4[4] = {a.x,a.y,a.z,a.w};
            float bv4[4] = {b.x,b.y,b.z,b.w};
            #pragma unroll
            for (int i = 0; i < 4; i++)
                #pragma unroll
                for (int j = 0; j < 4; j++)
                    acc[i][j] += av4[i]*bv4[j];
        }
        __syncthreads();
    }
    #pragma unroll
    for (int i = 0; i < 4; i++) {
        int m = m0 + (ty<<2) + i;
        if (m >= M) continue;
        #pragma unroll
        for (int j = 0; j < 4; j++) {
            int n = n0 + (tx<<2) + j;
            if (n >= N) continue;
            float v = acc[i][j] + (bias ? bias[n] : 0.f);
            if (relu) v = fmaxf(v, 0.f);
            C[(size_t)m*N + n] = v;
        }
    }
}

// ---------------- SGEMM with B transposed ----------------
__global__ __launch_bounds__(256)
void k_sgemm_nt(const float* __restrict__ A, const float* __restrict__ B,
                const float* __restrict__ bias, float* __restrict__ C,
                int M, int N, int K, int relu)
{
    __shared__ float As[16][64];
    __shared__ float Bs[16][68];
    int m0 = blockIdx.y * 64, n0 = blockIdx.x * 64;
    int t = threadIdx.x, ty = t >> 4, tx = t & 15;
    float acc[4][4] = {};
    int lr = t >> 2, lk = (t & 3) << 2;

    for (int k0 = 0; k0 < K; k0 += 16) {
        float4 av = make_float4(0.f,0.f,0.f,0.f);
        if (m0 + lr < M) av = *(const float4*)(A + (size_t)(m0+lr)*K + k0 + lk);
        As[lk+0][lr] = av.x; As[lk+1][lr] = av.y; As[lk+2][lr] = av.z; As[lk+3][lr] = av.w;
        float4 bv = make_float4(0.f,0.f,0.f,0.f);
        if (n0 + lr < N) bv = *(const float4*)(B + (size_t)(n0+lr)*K + k0 + lk);
        Bs[lk+0][lr] = bv.x; Bs[lk+1][lr] = bv.y; Bs[lk+2][lr] = bv.z; Bs[lk+3][lr] = bv.w;
        __syncthreads();
        #pragma unroll
        for (int kk = 0; kk < 16; kk++) {
            float4 a = *(const float4*)&As[kk][ty<<2];
            float4 b = *(const float4*)&Bs[kk][tx<<2];
            float av4[4] = {a.x,a.y,a.z,a.w};
            float bv4[4] = {b.x,b.y,b.z,b.w};
            #pragma unroll
            for (int i = 0; i < 4; i++)
                #pragma unroll
                for (int j = 0; j < 4; j++)
                    acc[i][j] += av4[i]*bv4[j];
        }
        __syncthreads();
    }
    #pragma unroll
    for (int i = 0; i < 4; i++) {
        int m = m0 + (ty<<2) + i;
        if (m >= M) continue;
        #pragma unroll
        for (int j = 0; j < 4; j++) {
            int n = n0 + (tx<<2) + j;
            if (n >= N) continue;
            float v = acc[i][j] + (bias ? bias[n] : 0.f);
            if (relu) v = fmaxf(v, 0.f);
            C[(size_t)m*N + n] = v;
        }
    }
}

// ---------------- fp16 mma GEMM: C = A(MxK) x B(KxN) + bias (opt relu) ----------------
// CTA 128M x 64N, 8 warps = 4(m) x 2(n), warp tile 32x32 = 2x4 m16n8k16.
// K multiple of 16; N guarded; M guarded.
__global__ __launch_bounds__(256)
void k_gemm_f16(const float* __restrict__ A, const float* __restrict__ B,
                const float* __restrict__ bias, float* __restrict__ C,
                int M, int N, int K, int relu)
{
    __shared__ uint32_t As2[128*9];   // [m][kpair], stride 9
    __shared__ uint32_t Bs2[8][68];   // [kpair][n]
    int t = threadIdx.x;
    int wid = t >> 5, l = t & 31;
    int warp_m = wid & 3, warp_n = wid >> 2;
    int qrow = l >> 2, qcol = l & 3;
    int m0 = blockIdx.y * 128, n0 = blockIdx.x * 64;

    float acc[2][4][4];
    #pragma unroll
    for (int a = 0; a < 2; a++)
        #pragma unroll
        for (int b = 0; b < 4; b++)
            #pragma unroll
            for (int c = 0; c < 4; c++) acc[a][b][c] = 0.f;

    // loader indices: A: e=i*256+t -> row=e>>3, kp=e&7 (4 float2 each)
    //                 B: e=i*256+t -> kp=e>>6, n=e&63  (2 half2 each, 2 loads apiece)
    float2 ldA[4]; float ldB0[2], ldB1[2];
    #pragma unroll
    for (int i = 0; i < 4; i++) {
        int e = i*256 + t, row = e >> 3, kp = e & 7;
        ldA[i] = (m0 + row < M) ? *(const float2*)(A + (size_t)(m0+row)*K + 2*kp)
                                : make_float2(0.f, 0.f);
    }
    #pragma unroll
    for (int i = 0; i < 2; i++) {
        int e = i*256 + t, kp = e >> 6, n = e & 63;
        bool nv = (n0 + n < N);
        ldB0[i] = nv ? B[(size_t)(2*kp  )*N + n0 + n] : 0.f;
        ldB1[i] = nv ? B[(size_t)(2*kp+1)*N + n0 + n] : 0.f;
    }

    int nk = K >> 4;
    for (int c = 0; c < nk; c++) {
        #pragma unroll
        for (int i = 0; i < 4; i++) {
            int e = i*256 + t, row = e >> 3, kp = e & 7;
            As2[row*9 + kp] = h2pack(ldA[i].x, ldA[i].y);
        }
        #pragma unroll
        for (int i = 0; i < 2; i++) {
            int e = i*256 + t, kp = e >> 6, n = e & 63;
            Bs2[kp][n] = h2pack(ldB0[i], ldB1[i]);
        }
        __syncthreads();
        if (c + 1 < nk) {
            int k0 = (c + 1) << 4;
            #pragma unroll
            for (int i = 0; i < 4; i++) {
                int e = i*256 + t, row = e >> 3, kp = e & 7;
                ldA[i] = (m0 + row < M) ? *(const float2*)(A + (size_t)(m0+row)*K + k0 + 2*kp)
                                        : make_float2(0.f, 0.f);
            }
            #pragma unroll
            for (int i = 0; i < 2; i++) {
                int e = i*256 + t, kp = e >> 6, n = e & 63;
                bool nv = (n0 + n < N);
                ldB0[i] = nv ? B[(size_t)(k0 + 2*kp  )*N + n0 + n] : 0.f;
                ldB1[i] = nv ? B[(size_t)(k0 + 2*kp+1)*N + n0 + n] : 0.f;
            }
        }
        #pragma unroll
        for (int mt = 0; mt < 2; mt++) {
            int m = warp_m*32 + mt*16;
            uint32_t a0 = As2[(m+qrow  )*9 + qcol    ];
            uint32_t a1 = As2[(m+qrow+8)*9 + qcol    ];
            uint32_t a2 = As2[(m+qrow  )*9 + qcol + 4];
            uint32_t a3 = As2[(m+qrow+8)*9 + qcol + 4];
            #pragma unroll
            for (int nt = 0; nt < 4; nt++) {
                int n = warp_n*32 + nt*8 + qrow;
                uint32_t b0 = Bs2[qcol    ][n];
                uint32_t b1 = Bs2[qcol + 4][n];
                MMA_F16(acc[mt][nt], a0, a1, a2, a3, b0, b1);
            }
        }
        __syncthreads();
    }

    #pragma unroll
    for (int mt = 0; mt < 2; mt++) {
        int mrow = m0 + warp_m*32 + mt*16 + qrow;
        #pragma unroll
        for (int nt = 0; nt < 4; nt++) {
            int n = n0 + warp_n*32 + nt*8 + qcol*2;
            if (n >= N) continue;
            float b0v = bias ? bias[n]   : 0.f;
            float b1v = bias ? bias[n+1] : 0.f;
            float v0 = acc[mt][nt][0] + b0v, v1 = acc[mt][nt][1] + b1v;
            float v2 = acc[mt][nt][2] + b0v, v3 = acc[mt][nt][3] + b1v;
            if (relu) { v0=fmaxf(v0,0.f); v1=fmaxf(v1,0.f); v2=fmaxf(v2,0.f); v3=fmaxf(v3,0.f); }
            if (mrow < M)     *(float2*)&C[(size_t)mrow*N + n]     = make_float2(v0, v1);
            if (mrow + 8 < M) *(float2*)&C[(size_t)(mrow+8)*N + n] = make_float2(v2, v3);
        }
    }
}

// ---------------- deconv via fp16 mma ----------------
// grid (313, 2, 8). CTA 128 oc x 64 sp. Wd layout [oc][ic][tap] (stride 8).
__global__ __launch_bounds__(256)
void k_deconv_f16(const float* __restrict__ Wd, const float* __restrict__ V,
                  float* __restrict__ X1)
{
    __shared__ uint32_t As2[128*9];
    __shared__ uint32_t Bs2[8][68];
    int t = threadIdx.x;
    int wid = t >> 5, l = t & 31;
    int warp_m = wid & 3, warp_n = wid >> 2;
    int qrow = l >> 2, qcol = l & 3;
    int m0 = blockIdx.y * 128, n0 = blockIdx.x * 64;
    int tap = blockIdx.z;
    int k1 = tap>>2, k2 = (tap>>1)&1, k3 = tap&1;

    float acc[2][4][4];
    #pragma unroll
    for (int a = 0; a < 2; a++)
        #pragma unroll
        for (int b = 0; b < 4; b++)
            #pragma unroll
            for (int c = 0; c < 4; c++) acc[a][b][c] = 0.f;

    float ldA0[4], ldA1[4], ldB0[2], ldB1[2];
    #pragma unroll
    for (int i = 0; i < 4; i++) {
        int e = i*256 + t, row = e >> 3, kp = e & 7;
        const float* wp = Wd + (((size_t)(m0+row))*256 + 2*kp)*8 + tap;
        ldA0[i] = wp[0]; ldA1[i] = wp[8];
    }
    #pragma unroll
    for (int i = 0; i < 2; i++) {
        int e = i*256 + t, kp = e >> 6, n = e & 63;
        bool nv = (n0 + n < NSP);
        ldB0[i] = nv ? V[(size_t)(2*kp  )*NSP + n0 + n] : 0.f;
        ldB1[i] = nv ? V[(size_t)(2*kp+1)*NSP + n0 + n] : 0.f;
    }

    for (int c = 0; c < 16; c++) {       // K = 256
        #pragma unroll
        for (int i = 0; i < 4; i++) {
            int e = i*256 + t, row = e >> 3, kp = e & 7;
            As2[row*9 + kp] = h2pack(ldA0[i], ldA1[i]);
        }
        #pragma unroll
        for (int i = 0; i < 2; i++) {
            int e = i*256 + t, kp = e >> 6, n = e & 63;
            Bs2[kp][n] = h2pack(ldB0[i], ldB1[i]);
        }
        __syncthreads();
        if (c + 1 < 16) {
            int k0 = (c + 1) << 4;
            #pragma unroll
            for (int i = 0; i < 4; i++) {
                int e = i*256 + t, row = e >> 3, kp = e & 7;
                const float* wp = Wd + (((size_t)(m0+row))*256 + k0 + 2*kp)*8 + tap;
                ldA0[i] = wp[0]; ldA1[i] = wp[8];
            }
            #pragma unroll
            for (int i = 0; i < 2; i++) {
                int e = i*256 + t, kp = e >> 6, n = e & 63;
                bool nv = (n0 + n < NSP);
                ldB0[i] = nv ? V[(size_t)(k0 + 2*kp  )*NSP + n0 + n] : 0.f;
                ldB1[i] = nv ? V[(size_t)(k0 + 2*kp+1)*NSP + n0 + n] : 0.f;
            }
        }
        #pragma unroll
        for (int mt = 0; mt < 2; mt++) {
            int m = warp_m*32 + mt*16;
            uint32_t a0 = As2[(m+qrow  )*9 + qcol    ];
            uint32_t a1 = As2[(m+qrow+8)*9 + qcol    ];
            uint32_t a2 = As2[(m+qrow  )*9 + qcol + 4];
            uint32_t a3 = As2[(m+qrow+8)*9 + qcol + 4];
            #pragma unroll
            for (int nt = 0; nt < 4; nt++) {
                int n = warp_n*32 + nt*8 + qrow;
                uint32_t b0 = Bs2[qcol    ][n];
                uint32_t b1 = Bs2[qcol + 4][n];
                MMA_F16(acc[mt][nt], a0, a1, a2, a3, b0, b1);
            }
        }
        __syncthreads();
    }

    // scatter epilogue
    #pragma unroll
    for (int mt = 0; mt < 2; mt++) {
        int mrow = m0 + warp_m*32 + mt*16 + qrow;
        #pragma unroll
        for (int nt = 0; nt < 4; nt++) {
            int n = n0 + warp_n*32 + nt*8 + qcol*2;
            #pragma unroll
            for (int j = 0; j < 2; j++) {
                int col = n + j;
                if (col >= NSP) continue;
                int a_ = col/400, b_ = (col>>3)%50, c_ = col&7;
                size_t o = (size_t)(2*a_ + 1 - k1)*1600 + (2*b_ + 1 - k2)*16 + (2*c_ + 1 - k3);
                X1[(size_t)mrow*SP + o]     = acc[mt][nt][j];
                X1[(size_t)(mrow+8)*SP + o] = acc[mt][nt][2+j];
            }
        }
    }
}

// ---------------- feat += embeds ----------------
__global__ void k_add_embeds(float* __restrict__ feat, const float* __restrict__ cams,
                             const float* __restrict__ lvl)
{
    int i = blockIdx.x * blockDim.x + threadIdx.x;
    if (i >= CAMS*Lf*Dm) return;
    int d = i % Dm;
    int n = i / (Lf*Dm);
    feat[i] += cams[n*Dm + d] + lvl[d];
}

// ---------------- deformable sampling with fused softmax ----------------
__global__ void k_sample(const float* __restrict__ val, const float* __restrict__ off,
                         const float* __restrict__ att, float* __restrict__ agg)
{
    int q = blockIdx.x;
    int h = threadIdx.y;
    int lane = threadIdx.x;
    float refx = ((float)(q % 50) + 0.5f) * (22.f/50.f) - 0.5f;
    float refy = ((float)((q/50) % 50) + 0.5f) * (8.f/50.f) - 0.5f;
    const float* offq = off + (size_t)q*192 + h*24;
    const float* attq = att + (size_t)q*96  + h*12;

    float lg = (lane < 12) ? attq[lane] : -1e30f;
    float mx = lg;
    #pragma unroll
    for (int o = 16; o > 0; o >>= 1) mx = fmaxf(mx, __shfl_xor_sync(0xffffffffu, mx, o));
    float e = (lane < 12) ? expf(lg - mx) : 0.f;
    float ssum = e;
    #pragma unroll
    for (int o = 16; o > 0; o >>= 1) ssum += __shfl_xor_sync(0xffffffffu, ssum, o);
    float r = 1.f / ssum;

    float acc = 0.f;
    #pragma unroll
    for (int c = 0; c < CAMS; c++) {
        #pragma unroll
        for (int p = 0; p < PTS; p++) {
            float x = refx + offq[c*4 + p*2 + 0];
            float y = refy + offq[c*4 + p*2 + 1];
            float a = __shfl_sync(0xffffffffu, e, c*2 + p) * r;
            float x0f = floorf(x), y0f = floorf(y);
            float wx = x - x0f, wy = y - y0f;
            int x0 = (int)x0f, y0 = (int)y0f;
            int x0c = min(max(x0,   0), FW-1);
            int x1c = min(max(x0+1, 0), FW-1);
            int y0c = min(max(y0,   0), FH-1);
            int y1c = min(max(y0+1, 0), FH-1);
            const float* vb = val + (size_t)c*Lf*Dm + h*DHh + lane;
            float v00 = vb[(y0c*FW + x0c)*Dm];
            float v01 = vb[(y0c*FW + x1c)*Dm];
            float v10 = vb[(y1c*FW + x0c)*Dm];
            float v11 = vb[(y1c*FW + x1c)*Dm];
            acc += a * ((1.f-wx)*(1.f-wy)*v00 + wx*(1.f-wy)*v01
                      + (1.f-wx)*wy*v10      + wx*wy*v11);
        }
    }
    agg[(size_t)q*Dm + h*DHh + lane] = acc;
}

// ---------------- residual add + LayerNorm(256) ----------------
__global__ void k_ln_residual(float* __restrict__ q, const float* __restrict__ delta,
                              const float* __restrict__ g, const float* __restrict__ b)
{
    int row = blockIdx.x*8 + threadIdx.y;
    int lane = threadIdx.x;
    size_t base = (size_t)row * Dm;
    float v[8]; float s = 0.f;
    #pragma unroll
    for (int i = 0; i < 8; i++) {
        int d = lane + 32*i;
        v[i] = q[base+d] + delta[base+d];
        s += v[i];
    }
    #pragma unroll
    for (int o = 16; o > 0; o >>= 1) s += __shfl_xor_sync(0xffffffffu, s, o);
    float mean = s * (1.f/256.f);
    float s2 = 0.f;
    #pragma unroll
    for (int i = 0; i < 8; i++) { float d0 = v[i]-mean; s2 += d0*d0; }
    #pragma unroll
    for (int o = 16; o > 0; o >>= 1) s2 += __shfl_xor_sync(0xffffffffu, s2, o);
    float rstd = rsqrtf(s2*(1.f/256.f) + 1e-5f);
    #pragma unroll
    for (int i = 0; i < 8; i++) {
        int d = lane + 32*i;
        q[base+d] = (v[i]-mean)*rstd*g[d] + b[d];
    }
}

// ---------------- q -> vol ----------------
__global__ void k_vol(const float* __restrict__ q, float* __restrict__ vol)
{
    int i = blockIdx.x*blockDim.x + threadIdx.x;
    if (i >= Dm*NSP) return;
    int n = i % NSP, ch = i / NSP;
    int a = n/400, b = (n>>3)%50, c = n&7;
    vol[i] = q[((size_t)((c*50 + b)*50 + a))*Dm + ch];
}

// ---------------- GroupNorm: deterministic 2-stage ----------------
__global__ void k_gn_reduce(const float* __restrict__ x, int gc, int nblk)
{
    int g = blockIdx.x / nblk;
    int b = blockIdx.x % nblk;
    size_t E = (size_t)gc * SP;
    size_t chunk = E / nblk;
    const float4* p = (const float4*)(x + (size_t)g*E + (size_t)b*chunk);
    int n4 = (int)(chunk >> 2);
    float s = 0.f, sq = 0.f;
    for (int i = threadIdx.x; i < n4; i += 256) {
        float4 v = p[i];
        s  += v.x + v.y + v.z + v.w;
        sq += v.x*v.x + v.y*v.y + v.z*v.z + v.w*v.w;
    }
    __shared__ float sh[256], sh2[256];
    sh[threadIdx.x] = s; sh2[threadIdx.x] = sq;
    __syncthreads();
    for (int o = 128; o > 0; o >>= 1) {
        if (threadIdx.x < o) { sh[threadIdx.x] += sh[threadIdx.x+o]; sh2[threadIdx.x] += sh2[threadIdx.x+o]; }
        __syncthreads();
    }
    if (threadIdx.x == 0) { g_psum[blockIdx.x] = sh[0]; g_psq[blockIdx.x] = sh2[0]; }
}

__global__ void k_gn_finalize(int gc, int nblk)
{
    int g = threadIdx.x;
    if (g >= 16) return;
    float s = 0.f, sq = 0.f;
    for (int b = 0; b < nblk; b++) { s += g_psum[g*nblk+b]; sq += g_psq[g*nblk+b]; }
    float E = (float)gc * (float)SP;
    float m = s / E;
    float var = sq / E - m*m;
    g_mean[g] = m;
    g_rstd[g] = rsqrtf(var + 1e-5f);
}

__global__ void k_gn_norm_relu(float* __restrict__ x, const float* __restrict__ gamma,
                               const float* __restrict__ beta, int C, int gc)
{
    int i = blockIdx.x*blockDim.x + threadIdx.x;
    if (i >= C*SP) return;
    int ch = i / SP;
    int g = ch / gc;
    float v = (x[i] - g_mean[g]) * g_rstd[g] * gamma[ch] + beta[ch];
    x[i] = fmaxf(v, 0.f);
}

// ---------------- conv3 weight prepack: half2 k-pairs [tap][icc][p][oc] ----------------
__global__ void k_prepack_wh(const float* __restrict__ W, uint32_t* __restrict__ Wp)
{
    int i = blockIdx.x*blockDim.x + threadIdx.x;
    if (i >= 27*128*192) return;
    int oc  = i % 192;
    int p   = (i / 192) & 7;
    int icc = (i / 1536) & 15;
    int tap = i / 24576;
    int ic  = icc*16 + 2*p;
    float w0 = W[((size_t)oc*256 + ic  )*27 + tap];
    float w1 = W[((size_t)oc*256 + ic+1)*27 + tap];
    Wp[i] = h2pack(w0, w1);
}

// ---------------- conv3 via mma.sync fp16 m16n8k16 ----------------
__global__ __launch_bounds__(256)
void k_conv3_mma(const float* __restrict__ X, const uint32_t* __restrict__ Wph,
                 float* __restrict__ Out)
{
    __shared__ uint32_t As2[96*12];
    __shared__ uint32_t Bs2[8][260];

    int t = threadIdx.x;
    int wid = t >> 5, l = t & 31;
    int warp_m = wid & 1, warp_n = wid >> 1;
    int qrow = l >> 2, qcol = l & 3;
    int n0 = blockIdx.y * 256;
    int ocb = blockIdx.x * 96;

    int s = n0 + t;
    int w = s & 15, h = (s >> 4) % 100, d = s / 1600;

    int ofsA[3], smA[3];
    #pragma unroll
    for (int i = 0; i < 3; i++) {
        int e = i*256 + t;
        int m = e % 96, p = e / 96;
        ofsA[i] = p*192 + ocb + m;
        smA[i]  = m*12 + p;
    }

    float acc[3][8][4];
    #pragma unroll
    for (int a = 0; a < 3; a++)
        #pragma unroll
        for (int b = 0; b < 8; b++)
            #pragma unroll
            for (int c = 0; c < 4; c++) acc[a][b][c] = 0.f;

    float ldB[16];
    uint32_t ldA[3];
    int voff = 0; bool vvalid = false;

    {
        int iw = w - 1, ih = h - 1, id = d - 1;
        vvalid = (iw >= 0 && ih >= 0 && id >= 0);
        voff = id*1600 + ih*16 + iw;
        const float* xb = X + (vvalid ? voff : 0);
        #pragma unroll
        for (int j = 0; j < 16; j++)
            ldB[j] = vvalid ? xb[(size_t)j*SP] : 0.f;
        #pragma unroll
        for (int i = 0; i < 3; i++) ldA[i] = Wph[ofsA[i]];
    }

    for (int c = 0; c < 432; c++) {
        #pragma unroll
        for (int p = 0; p < 8; p++)
            Bs2[p][t] = h2pack(ldB[2*p], ldB[2*p+1]);
        #pragma unroll
        for (int i = 0; i < 3; i++)
            As2[smA[i]] = ldA[i];
        __syncthreads();

        if (c + 1 < 432) {
            int cn = c + 1;
            int tap = cn >> 4, icc = cn & 15;
            if (icc == 0) {
                int kd = tap/9, kh = (tap%9)/3, kw = tap%3;
                int iw = w + kw - 1, ih = h + kh - 1, id = d + kd - 1;
                vvalid = (iw >= 0 && iw < 16 && ih >= 0 && ih < 100 && id >= 0 && id < 100);
                voff = id*1600 + ih*16 + iw;
            }
            const float* xb = X + (size_t)(icc*16)*SP + (vvalid ? voff : 0);
            #pragma unroll
            for (int j = 0; j < 16; j++)
                ldB[j] = vvalid ? xb[(size_t)j*SP] : 0.f;
            const uint32_t* wb = Wph + (size_t)(tap*16 + icc)*1536;
            #pragma unroll
            for (int i = 0; i < 3; i++) ldA[i] = wb[ofsA[i]];
        }

        #pragma unroll
        for (int mt = 0; mt < 3; mt++) {
            int m = warp_m*48 + mt*16;
            uint32_t a0 = As2[(m+qrow  )*12 + qcol    ];
            uint32_t a1 = As2[(m+qrow+8)*12 + qcol    ];
            uint32_t a2 = As2[(m+qrow  )*12 + qcol + 4];
            uint32_t a3 = As2[(m+qrow+8)*12 + qcol + 4];
            #pragma unroll
            for (int nt = 0; nt < 8; nt++) {
                int n = warp_n*64 + nt*8 + qrow;
                uint32_t b0 = Bs2[qcol    ][n];
                uint32_t b1 = Bs2[qcol + 4][n];
                MMA_F16(acc[mt][nt], a0, a1, a2, a3, b0, b1);
            }
        }
        __syncthreads();
    }

    #pragma unroll
    for (int mt = 0; mt < 3; mt++) {
        int oc0 = ocb + warp_m*48 + mt*16 + qrow;
        #pragma unroll
        for (int nt = 0; nt < 8; nt++) {
            int sp = n0 + warp_n*64 + nt*8 + qcol*2;
            *(float2*)&Out[(size_t)oc0*SP + sp]     = make_float2(acc[mt][nt][0], acc[mt][nt][1]);
            *(float2*)&Out[(size_t)(oc0+8)*SP + sp] = make_float2(acc[mt][nt][2], acc[mt][nt][3]);
        }
    }
}

// ---------------- host launcher ----------------
extern "C" void kernel_launch(void* const* d_in, const int* in_sizes, int n_in,
                              void* d_out, int out_size)
{
    const float* camera_x = (const float*)d_in[0];
    const int*   ids      = (const int*)  d_in[1];
    const float* mask_tok = (const float*)d_in[4];
    const float* vol_emb  = (const float*)d_in[5];
    const float* W_tc     = (const float*)d_in[6];
    const float* b_tc     = (const float*)d_in[7];
    const float* cams_e   = (const float*)d_in[8];
    const float* lvl_e    = (const float*)d_in[9];
    const float* W_off    = (const float*)d_in[10];
    const float* b_off    = (const float*)d_in[11];
    const float* W_att    = (const float*)d_in[12];
    const float* b_att    = (const float*)d_in[13];
    const float* W_val    = (const float*)d_in[14];
    const float* b_val    = (const float*)d_in[15];
    const float* W_out    = (const float*)d_in[16];
    const float* b_out    = (const float*)d_in[17];
    const float* ln1g     = (const float*)d_in[18];
    const float* ln1b     = (const float*)d_in[19];
    const float* W_ff1    = (const float*)d_in[20];
    const float* b_ff1    = (const float*)d_in[21];
    const float* W_ff2    = (const float*)d_in[22];
    const float* b_ff2    = (const float*)d_in[23];
    const float* ln2g     = (const float*)d_in[24];
    const float* ln2b     = (const float*)d_in[25];
    const float* deconv_w = (const float*)d_in[26];
    const float* gn1g     = (const float*)d_in[27];
    const float* gn1b     = (const float*)d_in[28];
    const float* conv3_w  = (const float*)d_in[29];
    const float* gn2g     = (const float*)d_in[30];
    const float* gn2b     = (const float*)d_in[31];
    float* out = (float*)d_out;

    float *full,*feat,*valb,*q,*off,*att,*agg,*hid,*delta,*vol,*x1;
    uint32_t *wph;
    cudaGetSymbolAddress((void**)&full,  g_full);
    cudaGetSymbolAddress((void**)&feat,  g_feat);
    cudaGetSymbolAddress((void**)&valb,  g_valb);
    cudaGetSymbolAddress((void**)&q,     g_q);
    cudaGetSymbolAddress((void**)&off,   g_off);
    cudaGetSymbolAddress((void**)&att,   g_att);
    cudaGetSymbolAddress((void**)&agg,   g_agg);
    cudaGetSymbolAddress((void**)&hid,   g_hid);
    cudaGetSymbolAddress((void**)&delta, g_delta);
    cudaGetSymbolAddress((void**)&vol,   g_vol);
    cudaGetSymbolAddress((void**)&x1,    g_x1);
    cudaGetSymbolAddress((void**)&wph,   g_wph);

    int write_camx = (out_size >= X_ELEMS + CAMX_ELEMS) ? 1 : 0;
    float* camx = out + X_ELEMS;

    // 1) restore + cam_x
    k_build_full<<<(CAMS*Lf*IN_C + 255)/256, 256>>>(camera_x, ids, mask_tok, full, camx, write_camx);

    // 1b) prepack conv3 weights (fp16)
    k_prepack_wh<<<(27*128*192 + 255)/256, 256>>>(conv3_w, wph);

    // 2) feat = relu(full @ W_tc^T + b_tc) + embeds
    k_sgemm_nt<<<dim3(4, 17), 256>>>(full, W_tc, b_tc, feat, CAMS*Lf, Dm, IN_C, 1);
    k_add_embeds<<<(CAMS*Lf*Dm + 255)/256, 256>>>(feat, cams_e, lvl_e);

    // 3) q = vol_emb
    cudaMemcpyAsync(q, vol_emb, sizeof(float)*(size_t)NQ*Dm, cudaMemcpyDeviceToDevice, 0);

    // 4) deformable layers (fp16 tensor cores)
    for (int l = 0; l < LAYERS; l++) {
        k_sgemm_nn<<<dim3(4, 17),  256>>>(feat, W_val + (size_t)l*Dm*Dm,  b_val + l*Dm,  valb, CAMS*Lf, Dm,  Dm, 0);
        k_gemm_f16<<<dim3(3, 157), 256>>>(q,   W_off + (size_t)l*Dm*192, b_off + l*192, off,  NQ, 192, Dm, 0);
        k_gemm_f16<<<dim3(2, 157), 256>>>(q,   W_att + (size_t)l*Dm*96,  b_att + l*96,  att,  NQ, 96,  Dm, 0);
        k_sample<<<NQ, dim3(32, 8)>>>(valb, off, att, agg);
        k_gemm_f16<<<dim3(4, 157), 256>>>(agg, W_out + (size_t)l*Dm*Dm, b_out + l*Dm, delta, NQ, Dm, Dm, 0);
        k_ln_residual<<<NQ/8, dim3(32, 8)>>>(q, delta, ln1g + l*Dm, ln1b + l*Dm);
        k_gemm_f16<<<dim3(8, 157), 256>>>(q,   W_ff1 + (size_t)l*Dm*FFNd, b_ff1 + l*FFNd, hid,   NQ, FFNd, Dm,   1);
        k_gemm_f16<<<dim3(4, 157), 256>>>(hid, W_ff2 + (size_t)l*FFNd*Dm, b_ff2 + l*Dm,   delta, NQ, Dm,   FFNd, 0);
        k_ln_residual<<<NQ/8, dim3(32, 8)>>>(q, delta, ln2g + l*Dm, ln2b + l*Dm);
    }

    // 5) vol
    k_vol<<<(Dm*NSP + 255)/256, 256>>>(q, vol);

    // 6) deconv -> x1 (fp16)
    k_deconv_f16<<<dim3(313, 2, 8), 256>>>(deconv_w, vol, x1);

    // 7) GN1 + relu
    k_gn_reduce<<<16*32, 256>>>(x1, 16, 32);
    k_gn_finalize<<<1, 32>>>(16, 32);
    k_gn_norm_relu<<<(Dm*SP + 255)/256, 256>>>(x1, gn1g, gn1b, Dm, 16);

    // 8) conv3 via mma.sync fp16
    k_conv3_mma<<<dim3(2, 625), 256>>>(x1, wph, out);

    // 9) GN2 + relu
    k_gn_reduce<<<16*32, 256>>>(out, 12, 32);
    k_gn_finalize<<<1, 32>>>(12, 32);
    k_gn_norm_relu<<<(192*SP + 255)/256, 256>>>(out, gn2g, gn2b, 192, 12);
}